// round 10
// baseline (speedup 1.0000x reference)
#include <cuda_runtime.h>
#include <cuda_fp16.h>
#include <cstdint>
#include <math.h>

// Problem constants
#define DD    1024
#define NTOK  131072      // 32*4096
#define BATCH 32
#define SEQ   4096

// GEMM tile config (fp16, K = 1024): 256x128 tile, 512 threads, 16 warps (8 M x 2 N)
#define BM 256
#define BN 128
#define BK 64
#define KTOT 1024
#define KTILES (KTOT / BK)        // 16
#define NSTAGE 3
#define NTHR 512

#define A_ROW_H (BK + 8)           // 72 halves = 144 B
#define B_ROW_H (BN + 8)           // 136 halves = 272 B
#define A_STAGE_B (BM * A_ROW_H * 2)            // 36864
#define B_STAGE_B (BK * B_ROW_H * 2)            // 17408
#define STAGE_B   (A_STAGE_B + B_STAGE_B)       // 54272
#define SMEM_DYN  (NSTAGE * STAGE_B)            // 162816

// ------------------------- device globals (scratch) -------------------------
__device__ __align__(256) __half g_xh [(size_t)NTOK * DD];  // x fp16 [n][k]
__device__ __align__(256) __half g_P  [(size_t)NTOK * DD];  // probs  fp16
__device__ __align__(256) __half g_BA [(size_t)DD * DD];    // L      [k][n] fp16
__device__ __align__(256) __half g_BB [(size_t)DD * DD];    // MW1    [k][n] fp16
__device__ __align__(256) __half g_Mh [(size_t)DD * DD];    // M fp16 [m][k]
__device__ __align__(256) __half g_w1h[(size_t)DD * DD];    // w1 fp16 [k][n]
__device__ __align__(256) float  g_M  [(size_t)DD * DD];    // M fp32 [k][d]
__device__ float g_poolP[BATCH * DD];
__device__ float g_poolH[BATCH * DD];

// ------------------------- helpers -------------------------
__device__ __forceinline__ uint32_t h2u(__half2 v) {
    uint32_t r; memcpy(&r, &v, 4); return r;
}
__device__ __forceinline__ unsigned smem_u32(const void* p) {
    return (unsigned)__cvta_generic_to_shared(p);
}
__device__ __forceinline__ void cp16(unsigned dst, const void* src) {
    asm volatile("cp.async.cg.shared.global [%0], [%1], 16;\n" :: "r"(dst), "l"(src));
}
__device__ __forceinline__ void cp_commit() { asm volatile("cp.async.commit_group;\n"); }

__device__ __forceinline__ void ldsm4(uint32_t &r0, uint32_t &r1, uint32_t &r2, uint32_t &r3, unsigned a) {
    asm volatile("ldmatrix.sync.aligned.m8n8.x4.shared.b16 {%0,%1,%2,%3},[%4];\n"
                 : "=r"(r0), "=r"(r1), "=r"(r2), "=r"(r3) : "r"(a));
}
__device__ __forceinline__ void ldsm4t(uint32_t &r0, uint32_t &r1, uint32_t &r2, uint32_t &r3, unsigned a) {
    asm volatile("ldmatrix.sync.aligned.m8n8.x4.trans.shared.b16 {%0,%1,%2,%3},[%4];\n"
                 : "=r"(r0), "=r"(r1), "=r"(r2), "=r"(r3) : "r"(a));
}
__device__ __forceinline__ void mma16816(float* c, const uint32_t* a, const uint32_t* b) {
    asm volatile("mma.sync.aligned.m16n8k16.row.col.f32.f16.f16.f32 "
                 "{%0,%1,%2,%3},{%4,%5,%6,%7},{%8,%9},{%0,%1,%2,%3};\n"
                 : "+f"(c[0]), "+f"(c[1]), "+f"(c[2]), "+f"(c[3])
                 : "r"(a[0]), "r"(a[1]), "r"(a[2]), "r"(a[3]), "r"(b[0]), "r"(b[1]));
}

// ------------------------- prep kernels -------------------------

__global__ void k_convert_x(const float* __restrict__ x) {
    size_t i = ((size_t)blockIdx.x * blockDim.x + threadIdx.x) * 8;
    float4 a = *reinterpret_cast<const float4*>(x + i);
    float4 b = *reinterpret_cast<const float4*>(x + i + 4);
    uint4 o;
    o.x = h2u(__floats2half2_rn(a.x, a.y));
    o.y = h2u(__floats2half2_rn(a.z, a.w));
    o.z = h2u(__floats2half2_rn(b.x, b.y));
    o.w = h2u(__floats2half2_rn(b.z, b.w));
    *reinterpret_cast<uint4*>(&g_xh[i]) = o;
}

// Combined: L (first 1M ids), M (next 1M ids), pool zeroing (first 32K ids also zero)
__global__ void k_build_LM(const float* __restrict__ wq, const float* __restrict__ kv,
                           const float* __restrict__ wo) {
    int idx = blockIdx.x * blockDim.x + threadIdx.x;     // 2M
    if (idx < BATCH * DD) { g_poolP[idx] = 0.f; g_poolH[idx] = 0.f; }
    if (idx < DD * DD) {
        // L[d][c] = 0.125 * sum_j wq[d, h*64+j] * kv[r, h*64+j]
        int d = idx >> 10, c = idx & 1023;
        int h = c >> 6, r = c & 63;
        const float* a = wq + (size_t)d * DD + h * 64;
        const float* k = kv + (size_t)r * DD + h * 64;
        float s = 0.f;
        #pragma unroll 16
        for (int j = 0; j < 64; j++) s += a[j] * k[j];
        g_BA[(size_t)d * DD + c] = __float2half_rn(s * 0.125f);
    } else {
        // M[k][d] = sum_j kv[r, h*64+j] * wo[h*64+j, d]
        int t = idx - DD * DD;
        int row = t >> 10, d = t & 1023;
        int h = row >> 6, r = row & 63;
        const float* kvp = kv + (size_t)r * DD + h * 64;
        float s = 0.f;
        #pragma unroll 8
        for (int j = 0; j < 64; j++) s += kvp[j] * wo[(size_t)(h * 64 + j) * DD + d];
        g_M[(size_t)row * DD + d] = s;
    }
}

// fp32 -> fp16 for M and w1 (2M elements total)
__global__ void k_convert_mw(const float* __restrict__ w1) {
    size_t i = ((size_t)blockIdx.x * blockDim.x + threadIdx.x) * 8;
    const size_t n1 = (size_t)DD * DD;
    const float* src = (i < n1) ? (g_M + i) : (w1 + (i - n1));
    __half* dst = (i < n1) ? (g_Mh + i) : (g_w1h + (i - n1));
    float4 a = *reinterpret_cast<const float4*>(src);
    float4 b = *reinterpret_cast<const float4*>(src + 4);
    uint4 o;
    o.x = h2u(__floats2half2_rn(a.x, a.y));
    o.y = h2u(__floats2half2_rn(a.z, a.w));
    o.z = h2u(__floats2half2_rn(b.x, b.y));
    o.w = h2u(__floats2half2_rn(b.z, b.w));
    *reinterpret_cast<uint4*>(dst) = o;
}

// ------------------------- main fp16 MMA GEMM (256x128 tile, 512 thr) -------------------------
// EPI=0: softmax -> store P + atomic col-sums to g_poolP
// EPI=1: bias+GELU -> atomic col-sums to g_poolH only (no store)
// EPI=2: plain fp16 store (used for MW1 = M @ w1)

__device__ __forceinline__ void fill_stage(const __half* __restrict__ A,
                                           const __half* __restrict__ Bm,
                                           uint32_t aSm, uint32_t bSm,
                                           int tid, int rowbase, int colbase, int k0) {
    // A: 256 rows x 64 k  (8 x 16B per row) = 2048 cp16
    #pragma unroll
    for (int i = 0; i < 4; i++) {
        int e = tid + i * NTHR;             // 0..2047
        int r = e >> 3, sg = e & 7;
        cp16(aSm + r * (A_ROW_H * 2) + sg * 16,
             A + (size_t)(rowbase + r) * DD + k0 + sg * 8);
    }
    // B: 64 k-rows x 128 n  (16 x 16B per row) = 1024 cp16
    #pragma unroll
    for (int i = 0; i < 2; i++) {
        int e = tid + i * NTHR;             // 0..1023
        int r = e >> 4, sg = e & 15;
        cp16(bSm + r * (B_ROW_H * 2) + sg * 16,
             Bm + (size_t)(k0 + r) * DD + colbase + sg * 8);
    }
}

template <int EPI>
__global__ __launch_bounds__(NTHR, 1) void k_gemm(const __half* __restrict__ A,
                                                  const __half* __restrict__ Bm,
                                                  __half* __restrict__ Out,
                                                  const float* __restrict__ bias,
                                                  float* __restrict__ pool) {
    extern __shared__ __align__(16) char dsm[];
    const uint32_t base = smem_u32(dsm);

    const int tid  = threadIdx.x;
    const int lane = tid & 31;
    const int warp = tid >> 5;
    const int wm = warp & 7;     // 8 warps along M (32 rows each)
    const int wn = warp >> 3;    // 2 warps along N (64 cols each)
    const int rowbase = blockIdx.y * BM;
    const int colbase = blockIdx.x * BN;

    float acc[2][8][4];
    #pragma unroll
    for (int mi = 0; mi < 2; mi++)
        #pragma unroll
        for (int ni = 0; ni < 8; ni++)
            #pragma unroll
            for (int q = 0; q < 4; q++) acc[mi][ni][q] = 0.f;

    #pragma unroll
    for (int s = 0; s < NSTAGE - 1; s++) {
        uint32_t aSm = base + s * STAGE_B;
        fill_stage(A, Bm, aSm, aSm + A_STAGE_B, tid, rowbase, colbase, s * BK);
        cp_commit();
    }

    for (int kt = 0; kt < KTILES; kt++) {
        if (kt < KTILES - 1) asm volatile("cp.async.wait_group 1;\n" ::: "memory");
        else                 asm volatile("cp.async.wait_group 0;\n" ::: "memory");
        __syncthreads();
        if (kt + NSTAGE - 1 < KTILES) {
            int s = (kt + NSTAGE - 1) % NSTAGE;
            uint32_t aSm = base + s * STAGE_B;
            fill_stage(A, Bm, aSm, aSm + A_STAGE_B, tid, rowbase, colbase, (kt + NSTAGE - 1) * BK);
            cp_commit();
        }
        const int cur = kt % NSTAGE;
        const uint32_t aSm = base + cur * STAGE_B;
        const uint32_t bSm = aSm + A_STAGE_B;
        #pragma unroll
        for (int ks = 0; ks < 4; ks++) {
            const int k0 = ks * 16;
            uint32_t af[2][4];
            #pragma unroll
            for (int mi = 0; mi < 2; mi++) {
                unsigned ad = aSm + (wm * 32 + mi * 16 + (lane & 15)) * (A_ROW_H * 2)
                            + (k0 + (lane >> 4) * 8) * 2;
                ldsm4(af[mi][0], af[mi][1], af[mi][2], af[mi][3], ad);
            }
            uint32_t bf[8][2];
            #pragma unroll
            for (int nj = 0; nj < 4; nj++) {
                unsigned bd = bSm + (k0 + (lane & 15)) * (B_ROW_H * 2)
                            + (wn * 64 + nj * 16 + (lane >> 4) * 8) * 2;
                uint32_t r0, r1, r2, r3;
                ldsm4t(r0, r1, r2, r3, bd);
                bf[nj * 2][0] = r0; bf[nj * 2][1] = r1;
                bf[nj * 2 + 1][0] = r2; bf[nj * 2 + 1][1] = r3;
            }
            #pragma unroll
            for (int mi = 0; mi < 2; mi++)
                #pragma unroll
                for (int ni = 0; ni < 8; ni++)
                    mma16816(acc[mi][ni], af[mi], bf[ni]);
        }
    }

    // ---------------- epilogue ----------------
    const int cb = colbase + wn * 64 + (lane & 3) * 2;

    if (EPI == 0) {
        // softmax over this warp's 64-column chunk (one head); probs left in acc
        #pragma unroll
        for (int mi = 0; mi < 2; mi++) {
            float mx0 = -1e30f, mx1 = -1e30f;
            #pragma unroll
            for (int ni = 0; ni < 8; ni++) {
                mx0 = fmaxf(mx0, fmaxf(acc[mi][ni][0], acc[mi][ni][1]));
                mx1 = fmaxf(mx1, fmaxf(acc[mi][ni][2], acc[mi][ni][3]));
            }
            mx0 = fmaxf(mx0, __shfl_xor_sync(0xffffffffu, mx0, 1));
            mx0 = fmaxf(mx0, __shfl_xor_sync(0xffffffffu, mx0, 2));
            mx1 = fmaxf(mx1, __shfl_xor_sync(0xffffffffu, mx1, 1));
            mx1 = fmaxf(mx1, __shfl_xor_sync(0xffffffffu, mx1, 2));
            float s0 = 0.f, s1 = 0.f;
            #pragma unroll
            for (int ni = 0; ni < 8; ni++) {
                acc[mi][ni][0] = __expf(acc[mi][ni][0] - mx0); s0 += acc[mi][ni][0];
                acc[mi][ni][1] = __expf(acc[mi][ni][1] - mx0); s0 += acc[mi][ni][1];
                acc[mi][ni][2] = __expf(acc[mi][ni][2] - mx1); s1 += acc[mi][ni][2];
                acc[mi][ni][3] = __expf(acc[mi][ni][3] - mx1); s1 += acc[mi][ni][3];
            }
            s0 += __shfl_xor_sync(0xffffffffu, s0, 1);
            s0 += __shfl_xor_sync(0xffffffffu, s0, 2);
            s1 += __shfl_xor_sync(0xffffffffu, s1, 1);
            s1 += __shfl_xor_sync(0xffffffffu, s1, 2);
            float i0 = 1.f / s0, i1 = 1.f / s1;
            int ra = rowbase + wm * 32 + mi * 16 + (lane >> 2);
            #pragma unroll
            for (int ni = 0; ni < 8; ni++) {
                acc[mi][ni][0] *= i0; acc[mi][ni][1] *= i0;
                acc[mi][ni][2] *= i1; acc[mi][ni][3] *= i1;
                *reinterpret_cast<__half2*>(&Out[(size_t)ra * DD + cb + ni * 8]) =
                    __floats2half2_rn(acc[mi][ni][0], acc[mi][ni][1]);
                *reinterpret_cast<__half2*>(&Out[(size_t)(ra + 8) * DD + cb + ni * 8]) =
                    __floats2half2_rn(acc[mi][ni][2], acc[mi][ni][3]);
            }
        }
    } else if (EPI == 1) {
        // bias + exact GELU; values left in acc, nothing stored
        #pragma unroll
        for (int mi = 0; mi < 2; mi++) {
            #pragma unroll
            for (int ni = 0; ni < 8; ni++) {
                int c = cb + ni * 8;
                float b0 = bias[c], b1v = bias[c + 1];
                float v0 = acc[mi][ni][0] + b0, v1 = acc[mi][ni][1] + b1v;
                float v2 = acc[mi][ni][2] + b0, v3 = acc[mi][ni][3] + b1v;
                acc[mi][ni][0] = 0.5f * v0 * (1.f + erff(v0 * 0.70710678118654752f));
                acc[mi][ni][1] = 0.5f * v1 * (1.f + erff(v1 * 0.70710678118654752f));
                acc[mi][ni][2] = 0.5f * v2 * (1.f + erff(v2 * 0.70710678118654752f));
                acc[mi][ni][3] = 0.5f * v3 * (1.f + erff(v3 * 0.70710678118654752f));
            }
        }
    } else {
        // plain fp16 store
        #pragma unroll
        for (int mi = 0; mi < 2; mi++) {
            int ra = rowbase + wm * 32 + mi * 16 + (lane >> 2);
            #pragma unroll
            for (int ni = 0; ni < 8; ni++) {
                *reinterpret_cast<__half2*>(&Out[(size_t)ra * DD + cb + ni * 8]) =
                    __floats2half2_rn(acc[mi][ni][0], acc[mi][ni][1]);
                *reinterpret_cast<__half2*>(&Out[(size_t)(ra + 8) * DD + cb + ni * 8]) =
                    __floats2half2_rn(acc[mi][ni][2], acc[mi][ni][3]);
            }
        }
    }

    if (EPI == 0 || EPI == 1) {
        // column sums of this warp's 32-row x 64-col chunk -> atomic pool add
        const int bidx = rowbase >> 12;                    // batch (4096 rows each)
        float t0[8], t1[8];
        #pragma unroll
        for (int ni = 0; ni < 8; ni++) {
            t0[ni] = acc[0][ni][0] + acc[0][ni][2] + acc[1][ni][0] + acc[1][ni][2];
            t1[ni] = acc[0][ni][1] + acc[0][ni][3] + acc[1][ni][1] + acc[1][ni][3];
            #pragma unroll
            for (int off = 4; off < 32; off <<= 1) {
                t0[ni] += __shfl_xor_sync(0xffffffffu, t0[ni], off);
                t1[ni] += __shfl_xor_sync(0xffffffffu, t1[ni], off);
            }
        }
        if (lane < 4) {
            float* dst = pool + bidx * DD + cb;            // cb uses lane&3 == lane
            #pragma unroll
            for (int ni = 0; ni < 8; ni++) {
                atomicAdd(dst + ni * 8,     t0[ni]);
                atomicAdd(dst + ni * 8 + 1, t1[ni]);
            }
        }
    }
}

// ------------------------- final -------------------------

__global__ void k_final_init(const float* __restrict__ b2, float* __restrict__ out) {
    int i = blockIdx.x * blockDim.x + threadIdx.x;
    if (i < BATCH * DD) out[i] = b2[i & (DD - 1)];
}

__global__ __launch_bounds__(128) void k_final_acc(const float* __restrict__ w2, float* __restrict__ out) {
    __shared__ float sH[BATCH][64];
    __shared__ float sP[BATCH][64];
    int d = blockIdx.x * 128 + threadIdx.x;
    int k0 = blockIdx.y * 64;
    for (int i = threadIdx.x; i < BATCH * 64; i += 128) {
        int bb = i >> 6, kk = i & 63;
        sH[bb][kk] = g_poolH[bb * DD + k0 + kk];
        sP[bb][kk] = g_poolP[bb * DD + k0 + kk];
    }
    __syncthreads();
    float a[BATCH];
    #pragma unroll
    for (int b = 0; b < BATCH; b++) a[b] = 0.f;
    for (int kk = 0; kk < 64; kk++) {
        float wv = w2[(size_t)(k0 + kk) * DD + d];
        float mv = g_M[(size_t)(k0 + kk) * DD + d];
        #pragma unroll
        for (int b = 0; b < BATCH; b++) a[b] += sH[b][kk] * wv + sP[b][kk] * mv;
    }
    const float inv = 1.0f / (float)SEQ;
    #pragma unroll
    for (int b = 0; b < BATCH; b++) atomicAdd(&out[b * DD + d], a[b] * inv);
}

// ------------------------- launcher -------------------------
extern "C" void kernel_launch(void* const* d_in, const int* in_sizes, int n_in,
                              void* d_out, int out_size) {
    const float* x  = (const float*)d_in[0];
    const float* wq = (const float*)d_in[1];
    const float* kv = (const float*)d_in[2];
    const float* wo = (const float*)d_in[3];
    const float* w1 = (const float*)d_in[4];
    const float* b1 = (const float*)d_in[5];
    const float* w2 = (const float*)d_in[6];
    const float* b2 = (const float*)d_in[7];
    float* out = (float*)d_out;
    (void)in_sizes; (void)n_in; (void)out_size;

    void *pXH = nullptr, *pP = nullptr, *pBA = nullptr, *pBB = nullptr;
    void *pMh = nullptr, *pW1h = nullptr, *pPP = nullptr, *pPH = nullptr;
    cudaGetSymbolAddress(&pXH, g_xh);
    cudaGetSymbolAddress(&pP,  g_P);
    cudaGetSymbolAddress(&pBA, g_BA);
    cudaGetSymbolAddress(&pBB, g_BB);
    cudaGetSymbolAddress(&pMh, g_Mh);
    cudaGetSymbolAddress(&pW1h, g_w1h);
    cudaGetSymbolAddress(&pPP, g_poolP);
    cudaGetSymbolAddress(&pPH, g_poolH);

    cudaFuncSetAttribute(k_gemm<0>, cudaFuncAttributeMaxDynamicSharedMemorySize, SMEM_DYN);
    cudaFuncSetAttribute(k_gemm<1>, cudaFuncAttributeMaxDynamicSharedMemorySize, SMEM_DYN);
    cudaFuncSetAttribute(k_gemm<2>, cudaFuncAttributeMaxDynamicSharedMemorySize, SMEM_DYN);

    dim3 gg(DD / BN, NTOK / BM);   // (8, 512)
    dim3 gw(DD / BN, DD / BM);     // (8, 4) for MW1

    k_convert_x<<<(int)(((size_t)NTOK * DD) / (256 * 8)), 256>>>(x);       // 0
    k_build_LM<<<8192, 256>>>(wq, kv, wo);                                 // 1 (L + M + pool zero)
    k_convert_mw<<<(int)((2 * (size_t)DD * DD) / (256 * 8)), 256>>>(w1);   // 2
    // GEMM A: logits = x @ L, fused softmax -> P, poolP atomics            // 3 (profiled slot)
    k_gemm<0><<<gg, NTHR, SMEM_DYN>>>((const __half*)pXH, (const __half*)pBA,
                                      (__half*)pP, nullptr, (float*)pPP);
    // MW1 = M @ w1 (fp16 tensor GEMM, plain store)                         // 4
    k_gemm<2><<<gw, NTHR, SMEM_DYN>>>((const __half*)pMh, (const __half*)pW1h,
                                      (__half*)pBB, nullptr, nullptr);
    // GEMM B: H = gelu(P @ MW1 + b1), poolH atomics only                   // 5
    k_gemm<1><<<gg, NTHR, SMEM_DYN>>>((const __half*)pP, (const __half*)pBB,
                                      nullptr, b1, (float*)pPH);
    k_final_init<<<(BATCH * DD + 255) / 256, 256>>>(b2, out);              // 6
    k_final_acc<<<dim3(DD / 128, DD / 64), 128>>>(w2, out);                // 7
}

// round 12
// speedup vs baseline: 1.0914x; 1.0914x over previous
#include <cuda_runtime.h>
#include <cuda_fp16.h>
#include <cstdint>
#include <math.h>

// Problem constants
#define DD    1024
#define NTOK  131072      // 32*4096
#define BATCH 32
#define SEQ   4096

// GEMM tile config (fp16, K = 1024)  -- R8-proven shape
#define BM 128
#define BN 128
#define BK 64
#define KTOT 1024
#define KTILES (KTOT / BK)        // 16
#define NSTAGE 3

#define A_ROW_H (BK + 8)           // 72 halves = 144 B
#define B_ROW_H (BN + 8)           // 136 halves = 272 B
#define A_STAGE_B (BM * A_ROW_H * 2)            // 18432
#define B_STAGE_B (BK * B_ROW_H * 2)            // 17408
#define STAGE_B   (A_STAGE_B + B_STAGE_B)       // 35840
#define SMEM_DYN  (NSTAGE * STAGE_B)            // 107520

// fused prep kernel id ranges (all multiples of 256)
#define IDS_X   16777216            // NTOK*DD/8
#define IDS_L   1048576
#define IDS_M   1048576
#define IDS_W1  131072              // DD*DD/8
#define IDS_ALL (IDS_X + IDS_L + IDS_M + IDS_W1)

// ------------------------- device globals (scratch) -------------------------
__device__ __align__(256) __half g_xh [(size_t)NTOK * DD];  // x fp16 [n][k]
__device__ __align__(256) __half g_P  [(size_t)NTOK * DD];  // probs  fp16
__device__ __align__(256) __half g_BA [(size_t)DD * DD];    // L      [k][n] fp16
__device__ __align__(256) __half g_BB [(size_t)DD * DD];    // MW1    [k][n] fp16
__device__ __align__(256) __half g_Mh [(size_t)DD * DD];    // M fp16 [m][k]
__device__ __align__(256) __half g_w1h[(size_t)DD * DD];    // w1 fp16 [k][n]
__device__ __align__(256) float  g_M  [(size_t)DD * DD];    // M fp32 [k][d]
__device__ float g_poolP[BATCH * DD];
__device__ float g_poolH[BATCH * DD];

// ------------------------- helpers -------------------------
__device__ __forceinline__ uint32_t h2u(__half2 v) {
    uint32_t r; memcpy(&r, &v, 4); return r;
}
__device__ __forceinline__ unsigned smem_u32(const void* p) {
    return (unsigned)__cvta_generic_to_shared(p);
}
__device__ __forceinline__ void cp16(unsigned dst, const void* src) {
    asm volatile("cp.async.cg.shared.global [%0], [%1], 16;\n" :: "r"(dst), "l"(src));
}
__device__ __forceinline__ void cp_commit() { asm volatile("cp.async.commit_group;\n"); }

__device__ __forceinline__ void ldsm4(uint32_t &r0, uint32_t &r1, uint32_t &r2, uint32_t &r3, unsigned a) {
    asm volatile("ldmatrix.sync.aligned.m8n8.x4.shared.b16 {%0,%1,%2,%3},[%4];\n"
                 : "=r"(r0), "=r"(r1), "=r"(r2), "=r"(r3) : "r"(a));
}
__device__ __forceinline__ void ldsm4t(uint32_t &r0, uint32_t &r1, uint32_t &r2, uint32_t &r3, unsigned a) {
    asm volatile("ldmatrix.sync.aligned.m8n8.x4.trans.shared.b16 {%0,%1,%2,%3},[%4];\n"
                 : "=r"(r0), "=r"(r1), "=r"(r2), "=r"(r3) : "r"(a));
}
__device__ __forceinline__ void mma16816(float* c, const uint32_t* a, const uint32_t* b) {
    asm volatile("mma.sync.aligned.m16n8k16.row.col.f32.f16.f16.f32 "
                 "{%0,%1,%2,%3},{%4,%5,%6,%7},{%8,%9},{%0,%1,%2,%3};\n"
                 : "+f"(c[0]), "+f"(c[1]), "+f"(c[2]), "+f"(c[3])
                 : "r"(a[0]), "r"(a[1]), "r"(a[2]), "r"(a[3]), "r"(b[0]), "r"(b[1]));
}

// ------------------------- fused prep kernel -------------------------
// ids [0, IDS_X): x->fp16 (8 elems); first 32K also zero pools
// ids [IDS_X, +IDS_L): L[d][c]
// ids [.., +IDS_M): M[k][d] -> g_M (fp32) and g_Mh (fp16)
// ids [.., +IDS_W1): w1 -> fp16 (8 elems)
__global__ void k_prep(const float* __restrict__ x, const float* __restrict__ wq,
                       const float* __restrict__ kv, const float* __restrict__ wo,
                       const float* __restrict__ w1) {
    int idx = blockIdx.x * blockDim.x + threadIdx.x;
    if (idx < IDS_X) {
        if (idx < BATCH * DD) { g_poolP[idx] = 0.f; g_poolH[idx] = 0.f; }
        size_t i = (size_t)idx * 8;
        float4 a = *reinterpret_cast<const float4*>(x + i);
        float4 b = *reinterpret_cast<const float4*>(x + i + 4);
        uint4 o;
        o.x = h2u(__floats2half2_rn(a.x, a.y));
        o.y = h2u(__floats2half2_rn(a.z, a.w));
        o.z = h2u(__floats2half2_rn(b.x, b.y));
        o.w = h2u(__floats2half2_rn(b.z, b.w));
        *reinterpret_cast<uint4*>(&g_xh[i]) = o;
    } else if (idx < IDS_X + IDS_L) {
        int t = idx - IDS_X;
        int d = t >> 10, c = t & 1023;
        int h = c >> 6, r = c & 63;
        const float* a = wq + (size_t)d * DD + h * 64;
        const float* k = kv + (size_t)r * DD + h * 64;
        float s = 0.f;
        #pragma unroll 16
        for (int j = 0; j < 64; j++) s += a[j] * k[j];
        g_BA[(size_t)d * DD + c] = __float2half_rn(s * 0.125f);
    } else if (idx < IDS_X + IDS_L + IDS_M) {
        int t = idx - IDS_X - IDS_L;
        int row = t >> 10, d = t & 1023;
        int h = row >> 6, r = row & 63;
        const float* kvp = kv + (size_t)r * DD + h * 64;
        float s = 0.f;
        #pragma unroll 8
        for (int j = 0; j < 64; j++) s += kvp[j] * wo[(size_t)(h * 64 + j) * DD + d];
        g_M [(size_t)row * DD + d] = s;
        g_Mh[(size_t)row * DD + d] = __float2half_rn(s);
    } else {
        int t = idx - IDS_X - IDS_L - IDS_M;     // 0..131071
        size_t i = (size_t)t * 8;
        float4 a = *reinterpret_cast<const float4*>(w1 + i);
        float4 b = *reinterpret_cast<const float4*>(w1 + i + 4);
        uint4 o;
        o.x = h2u(__floats2half2_rn(a.x, a.y));
        o.y = h2u(__floats2half2_rn(a.z, a.w));
        o.z = h2u(__floats2half2_rn(b.x, b.y));
        o.w = h2u(__floats2half2_rn(b.z, b.w));
        *reinterpret_cast<uint4*>(&g_w1h[i]) = o;
    }
}

// ------------------------- main fp16 MMA GEMM (K=1024, BK=64, 3-stage) -------------------------
// EPI=0: softmax -> store P + atomic col-sums to g_poolP
// EPI=1: bias+GELU -> atomic col-sums to g_poolH only (no store)
// EPI=2: plain fp16 store (used for MW1 = M @ w1)

__device__ __forceinline__ void fill_stage(const __half* __restrict__ A,
                                           const __half* __restrict__ Bm,
                                           uint32_t aSm, uint32_t bSm,
                                           int tid, int rowbase, int colbase, int k0) {
    #pragma unroll
    for (int i = 0; i < 4; i++) {
        int e = tid + i * 256;              // 0..1023
        int r = e >> 3, sg = e & 7;
        cp16(aSm + r * (A_ROW_H * 2) + sg * 16,
             A + (size_t)(rowbase + r) * DD + k0 + sg * 8);
    }
    #pragma unroll
    for (int i = 0; i < 4; i++) {
        int e = tid + i * 256;              // 0..1023
        int r = e >> 4, sg = e & 15;
        cp16(bSm + r * (B_ROW_H * 2) + sg * 16,
             Bm + (size_t)(k0 + r) * DD + colbase + sg * 8);
    }
}

template <int EPI>
__global__ __launch_bounds__(256, 2) void k_gemm(const __half* __restrict__ A,
                                                 const __half* __restrict__ Bm,
                                                 __half* __restrict__ Out,
                                                 const float* __restrict__ bias,
                                                 float* __restrict__ pool) {
    extern __shared__ __align__(16) char dsm[];
    const uint32_t base = smem_u32(dsm);

    const int tid  = threadIdx.x;
    const int lane = tid & 31;
    const int warp = tid >> 5;
    const int wm = warp & 3;     // 4 warps along M (32 rows each)
    const int wn = warp >> 2;    // 2 warps along N (64 cols each)
    const int rowbase = blockIdx.y * BM;
    const int colbase = blockIdx.x * BN;

    float acc[2][8][4];
    #pragma unroll
    for (int mi = 0; mi < 2; mi++)
        #pragma unroll
        for (int ni = 0; ni < 8; ni++)
            #pragma unroll
            for (int q = 0; q < 4; q++) acc[mi][ni][q] = 0.f;

    #pragma unroll
    for (int s = 0; s < NSTAGE - 1; s++) {
        uint32_t aSm = base + s * STAGE_B;
        fill_stage(A, Bm, aSm, aSm + A_STAGE_B, tid, rowbase, colbase, s * BK);
        cp_commit();
    }

    for (int kt = 0; kt < KTILES; kt++) {
        if (kt < KTILES - 1) asm volatile("cp.async.wait_group 1;\n" ::: "memory");
        else                 asm volatile("cp.async.wait_group 0;\n" ::: "memory");
        __syncthreads();
        if (kt + NSTAGE - 1 < KTILES) {
            int s = (kt + NSTAGE - 1) % NSTAGE;
            uint32_t aSm = base + s * STAGE_B;
            fill_stage(A, Bm, aSm, aSm + A_STAGE_B, tid, rowbase, colbase, (kt + NSTAGE - 1) * BK);
            cp_commit();
        }
        const int cur = kt % NSTAGE;
        const uint32_t aSm = base + cur * STAGE_B;
        const uint32_t bSm = aSm + A_STAGE_B;
        #pragma unroll
        for (int ks = 0; ks < 4; ks++) {
            const int k0 = ks * 16;
            uint32_t af[2][4];
            #pragma unroll
            for (int mi = 0; mi < 2; mi++) {
                unsigned ad = aSm + (wm * 32 + mi * 16 + (lane & 15)) * (A_ROW_H * 2)
                            + (k0 + (lane >> 4) * 8) * 2;
                ldsm4(af[mi][0], af[mi][1], af[mi][2], af[mi][3], ad);
            }
            uint32_t bf[8][2];
            #pragma unroll
            for (int nj = 0; nj < 4; nj++) {
                unsigned bd = bSm + (k0 + (lane & 15)) * (B_ROW_H * 2)
                            + (wn * 64 + nj * 16 + (lane >> 4) * 8) * 2;
                uint32_t r0, r1, r2, r3;
                ldsm4t(r0, r1, r2, r3, bd);
                bf[nj * 2][0] = r0; bf[nj * 2][1] = r1;
                bf[nj * 2 + 1][0] = r2; bf[nj * 2 + 1][1] = r3;
            }
            #pragma unroll
            for (int mi = 0; mi < 2; mi++)
                #pragma unroll
                for (int ni = 0; ni < 8; ni++)
                    mma16816(acc[mi][ni], af[mi], bf[ni]);
        }
    }

    // ---------------- epilogue ----------------
    const int cb = colbase + wn * 64 + (lane & 3) * 2;

    if (EPI == 0) {
        // softmax over this warp's 64-column chunk (one head); probs left in acc
        #pragma unroll
        for (int mi = 0; mi < 2; mi++) {
            float mx0 = -1e30f, mx1 = -1e30f;
            #pragma unroll
            for (int ni = 0; ni < 8; ni++) {
                mx0 = fmaxf(mx0, fmaxf(acc[mi][ni][0], acc[mi][ni][1]));
                mx1 = fmaxf(mx1, fmaxf(acc[mi][ni][2], acc[mi][ni][3]));
            }
            mx0 = fmaxf(mx0, __shfl_xor_sync(0xffffffffu, mx0, 1));
            mx0 = fmaxf(mx0, __shfl_xor_sync(0xffffffffu, mx0, 2));
            mx1 = fmaxf(mx1, __shfl_xor_sync(0xffffffffu, mx1, 1));
            mx1 = fmaxf(mx1, __shfl_xor_sync(0xffffffffu, mx1, 2));
            float s0 = 0.f, s1 = 0.f;
            #pragma unroll
            for (int ni = 0; ni < 8; ni++) {
                acc[mi][ni][0] = __expf(acc[mi][ni][0] - mx0); s0 += acc[mi][ni][0];
                acc[mi][ni][1] = __expf(acc[mi][ni][1] - mx0); s0 += acc[mi][ni][1];
                acc[mi][ni][2] = __expf(acc[mi][ni][2] - mx1); s1 += acc[mi][ni][2];
                acc[mi][ni][3] = __expf(acc[mi][ni][3] - mx1); s1 += acc[mi][ni][3];
            }
            s0 += __shfl_xor_sync(0xffffffffu, s0, 1);
            s0 += __shfl_xor_sync(0xffffffffu, s0, 2);
            s1 += __shfl_xor_sync(0xffffffffu, s1, 1);
            s1 += __shfl_xor_sync(0xffffffffu, s1, 2);
            float i0 = 1.f / s0, i1 = 1.f / s1;
            int ra = rowbase + wm * 32 + mi * 16 + (lane >> 2);
            #pragma unroll
            for (int ni = 0; ni < 8; ni++) {
                acc[mi][ni][0] *= i0; acc[mi][ni][1] *= i0;
                acc[mi][ni][2] *= i1; acc[mi][ni][3] *= i1;
                *reinterpret_cast<__half2*>(&Out[(size_t)ra * DD + cb + ni * 8]) =
                    __floats2half2_rn(acc[mi][ni][0], acc[mi][ni][1]);
                *reinterpret_cast<__half2*>(&Out[(size_t)(ra + 8) * DD + cb + ni * 8]) =
                    __floats2half2_rn(acc[mi][ni][2], acc[mi][ni][3]);
            }
        }
    } else if (EPI == 1) {
        // bias + exact GELU; values left in acc, nothing stored
        #pragma unroll
        for (int mi = 0; mi < 2; mi++) {
            #pragma unroll
            for (int ni = 0; ni < 8; ni++) {
                int c = cb + ni * 8;
                float b0 = bias[c], b1v = bias[c + 1];
                float v0 = acc[mi][ni][0] + b0, v1 = acc[mi][ni][1] + b1v;
                float v2 = acc[mi][ni][2] + b0, v3 = acc[mi][ni][3] + b1v;
                acc[mi][ni][0] = 0.5f * v0 * (1.f + erff(v0 * 0.70710678118654752f));
                acc[mi][ni][1] = 0.5f * v1 * (1.f + erff(v1 * 0.70710678118654752f));
                acc[mi][ni][2] = 0.5f * v2 * (1.f + erff(v2 * 0.70710678118654752f));
                acc[mi][ni][3] = 0.5f * v3 * (1.f + erff(v3 * 0.70710678118654752f));
            }
        }
    } else {
        // plain fp16 store
        #pragma unroll
        for (int mi = 0; mi < 2; mi++) {
            int ra = rowbase + wm * 32 + mi * 16 + (lane >> 2);
            #pragma unroll
            for (int ni = 0; ni < 8; ni++) {
                *reinterpret_cast<__half2*>(&Out[(size_t)ra * DD + cb + ni * 8]) =
                    __floats2half2_rn(acc[mi][ni][0], acc[mi][ni][1]);
                *reinterpret_cast<__half2*>(&Out[(size_t)(ra + 8) * DD + cb + ni * 8]) =
                    __floats2half2_rn(acc[mi][ni][2], acc[mi][ni][3]);
            }
        }
    }

    if (EPI == 0 || EPI == 1) {
        // column sums of this warp's 32-row x 64-col chunk -> atomic pool add
        const int bidx = rowbase >> 12;                    // batch (4096 rows each)
        float t0[8], t1[8];
        #pragma unroll
        for (int ni = 0; ni < 8; ni++) {
            t0[ni] = acc[0][ni][0] + acc[0][ni][2] + acc[1][ni][0] + acc[1][ni][2];
            t1[ni] = acc[0][ni][1] + acc[0][ni][3] + acc[1][ni][1] + acc[1][ni][3];
            #pragma unroll
            for (int off = 4; off < 32; off <<= 1) {
                t0[ni] += __shfl_xor_sync(0xffffffffu, t0[ni], off);
                t1[ni] += __shfl_xor_sync(0xffffffffu, t1[ni], off);
            }
        }
        if (lane < 4) {
            float* dst = pool + bidx * DD + cb;            // cb uses lane&3 == lane
            #pragma unroll
            for (int ni = 0; ni < 8; ni++) {
                atomicAdd(dst + ni * 8,     t0[ni]);
                atomicAdd(dst + ni * 8 + 1, t1[ni]);
            }
        }
    }
}

// ------------------------- final -------------------------

__global__ void k_final_init(const float* __restrict__ b2, float* __restrict__ out) {
    int i = blockIdx.x * blockDim.x + threadIdx.x;
    if (i < BATCH * DD) out[i] = b2[i & (DD - 1)];
}

__global__ __launch_bounds__(128) void k_final_acc(const float* __restrict__ w2, float* __restrict__ out) {
    __shared__ float sH[BATCH][64];
    __shared__ float sP[BATCH][64];
    int d = blockIdx.x * 128 + threadIdx.x;
    int k0 = blockIdx.y * 64;
    for (int i = threadIdx.x; i < BATCH * 64; i += 128) {
        int bb = i >> 6, kk = i & 63;
        sH[bb][kk] = g_poolH[bb * DD + k0 + kk];
        sP[bb][kk] = g_poolP[bb * DD + k0 + kk];
    }
    __syncthreads();
    float a[BATCH];
    #pragma unroll
    for (int b = 0; b < BATCH; b++) a[b] = 0.f;
    for (int kk = 0; kk < 64; kk++) {
        float wv = w2[(size_t)(k0 + kk) * DD + d];
        float mv = g_M[(size_t)(k0 + kk) * DD + d];
        #pragma unroll
        for (int b = 0; b < BATCH; b++) a[b] += sH[b][kk] * wv + sP[b][kk] * mv;
    }
    const float inv = 1.0f / (float)SEQ;
    #pragma unroll
    for (int b = 0; b < BATCH; b++) atomicAdd(&out[b * DD + d], a[b] * inv);
}

// ------------------------- launcher -------------------------
extern "C" void kernel_launch(void* const* d_in, const int* in_sizes, int n_in,
                              void* d_out, int out_size) {
    const float* x  = (const float*)d_in[0];
    const float* wq = (const float*)d_in[1];
    const float* kv = (const float*)d_in[2];
    const float* wo = (const float*)d_in[3];
    const float* w1 = (const float*)d_in[4];
    const float* b1 = (const float*)d_in[5];
    const float* w2 = (const float*)d_in[6];
    const float* b2 = (const float*)d_in[7];
    float* out = (float*)d_out;
    (void)in_sizes; (void)n_in; (void)out_size;

    void *pXH = nullptr, *pP = nullptr, *pBA = nullptr, *pBB = nullptr;
    void *pMh = nullptr, *pW1h = nullptr, *pPP = nullptr, *pPH = nullptr;
    cudaGetSymbolAddress(&pXH, g_xh);
    cudaGetSymbolAddress(&pP,  g_P);
    cudaGetSymbolAddress(&pBA, g_BA);
    cudaGetSymbolAddress(&pBB, g_BB);
    cudaGetSymbolAddress(&pMh, g_Mh);
    cudaGetSymbolAddress(&pW1h, g_w1h);
    cudaGetSymbolAddress(&pPP, g_poolP);
    cudaGetSymbolAddress(&pPH, g_poolH);

    cudaFuncSetAttribute(k_gemm<0>, cudaFuncAttributeMaxDynamicSharedMemorySize, SMEM_DYN);
    cudaFuncSetAttribute(k_gemm<1>, cudaFuncAttributeMaxDynamicSharedMemorySize, SMEM_DYN);
    cudaFuncSetAttribute(k_gemm<2>, cudaFuncAttributeMaxDynamicSharedMemorySize, SMEM_DYN);

    dim3 gg(DD / BN, NTOK / BM);   // (8, 1024)
    dim3 gw(DD / BN, DD / BM);     // (8, 8) for MW1

    // 0: fused prep (x->fp16 + pool zero + L + M/Mh + w1->fp16)
    k_prep<<<IDS_ALL / 256, 256>>>(x, wq, kv, wo, w1);
    // 1: GEMM A: logits = x @ L, fused softmax -> P, poolP atomics
    k_gemm<0><<<gg, 256, SMEM_DYN>>>((const __half*)pXH, (const __half*)pBA,
                                     (__half*)pP, nullptr, (float*)pPP);
    // 2: MW1 = M @ w1 (fp16 tensor GEMM, plain store)
    k_gemm<2><<<gw, 256, SMEM_DYN>>>((const __half*)pMh, (const __half*)pW1h,
                                     (__half*)pBB, nullptr, nullptr);
    // 3: GEMM B: H = gelu(P @ MW1 + b1), poolH atomics only  (profiled slot)
    k_gemm<1><<<gg, 256, SMEM_DYN>>>((const __half*)pP, (const __half*)pBB,
                                     nullptr, b1, (float*)pPH);
    // 4, 5: final
    k_final_init<<<(BATCH * DD + 255) / 256, 256>>>(b2, out);
    k_final_acc<<<dim3(DD / 128, DD / 64), 128>>>(w2, out);
}

// round 13
// speedup vs baseline: 1.0931x; 1.0016x over previous
#include <cuda_runtime.h>
#include <cuda_fp16.h>
#include <cstdint>
#include <math.h>

// Problem constants
#define DD    1024
#define NTOK  131072      // 32*4096
#define BATCH 32
#define SEQ   4096

// GEMM tile config (fp16, K = 1024)  -- R8-proven shape
#define BM 128
#define BN 128
#define BK 64
#define KTOT 1024
#define KTILES (KTOT / BK)        // 16
#define NSTAGE 3

#define A_ROW_H (BK + 8)           // 72 halves = 144 B
#define B_ROW_H (BN + 8)           // 136 halves = 272 B
#define A_STAGE_B (BM * A_ROW_H * 2)            // 18432
#define B_STAGE_B (BK * B_ROW_H * 2)            // 17408
#define STAGE_B   (A_STAGE_B + B_STAGE_B)       // 35840
#define SMEM_DYN  (NSTAGE * STAGE_B)            // 107520

// fused prep kernel id ranges (all multiples of 256)
#define IDS_X   16777216            // NTOK*DD/8
#define IDS_L   1048576
#define IDS_M   1048576
#define IDS_W1  131072              // DD*DD/8
#define IDS_ALL (IDS_X + IDS_L + IDS_M + IDS_W1)

// ------------------------- device globals (scratch) -------------------------
__device__ __align__(256) __half g_xh [(size_t)NTOK * DD];  // x fp16 [n][k]
__device__ __align__(256) __half g_P  [(size_t)NTOK * DD];  // probs  fp16
__device__ __align__(256) __half g_BA [(size_t)DD * DD];    // L      [k][n] fp16
__device__ __align__(256) __half g_BB [(size_t)DD * DD];    // MW1    [k][n] fp16
__device__ __align__(256) __half g_Mh [(size_t)DD * DD];    // M fp16 [m][k]
__device__ __align__(256) __half g_w1h[(size_t)DD * DD];    // w1 fp16 [k][n]
__device__ __align__(256) float  g_M  [(size_t)DD * DD];    // M fp32 [k][d]
__device__ float g_poolP[BATCH * DD];
__device__ float g_poolH[BATCH * DD];

// ------------------------- helpers -------------------------
__device__ __forceinline__ uint32_t h2u(__half2 v) {
    uint32_t r; memcpy(&r, &v, 4); return r;
}
__device__ __forceinline__ unsigned smem_u32(const void* p) {
    return (unsigned)__cvta_generic_to_shared(p);
}
__device__ __forceinline__ void cp16(unsigned dst, const void* src) {
    asm volatile("cp.async.cg.shared.global [%0], [%1], 16;\n" :: "r"(dst), "l"(src));
}
__device__ __forceinline__ void cp_commit() { asm volatile("cp.async.commit_group;\n"); }

__device__ __forceinline__ void ldsm4(uint32_t &r0, uint32_t &r1, uint32_t &r2, uint32_t &r3, unsigned a) {
    asm volatile("ldmatrix.sync.aligned.m8n8.x4.shared.b16 {%0,%1,%2,%3},[%4];\n"
                 : "=r"(r0), "=r"(r1), "=r"(r2), "=r"(r3) : "r"(a));
}
__device__ __forceinline__ void ldsm4t(uint32_t &r0, uint32_t &r1, uint32_t &r2, uint32_t &r3, unsigned a) {
    asm volatile("ldmatrix.sync.aligned.m8n8.x4.trans.shared.b16 {%0,%1,%2,%3},[%4];\n"
                 : "=r"(r0), "=r"(r1), "=r"(r2), "=r"(r3) : "r"(a));
}
__device__ __forceinline__ void mma16816(float* c, const uint32_t* a, const uint32_t* b) {
    asm volatile("mma.sync.aligned.m16n8k16.row.col.f32.f16.f16.f32 "
                 "{%0,%1,%2,%3},{%4,%5,%6,%7},{%8,%9},{%0,%1,%2,%3};\n"
                 : "+f"(c[0]), "+f"(c[1]), "+f"(c[2]), "+f"(c[3])
                 : "r"(a[0]), "r"(a[1]), "r"(a[2]), "r"(a[3]), "r"(b[0]), "r"(b[1]));
}

// ------------------------- fused prep kernel -------------------------
__global__ void k_prep(const float* __restrict__ x, const float* __restrict__ wq,
                       const float* __restrict__ kv, const float* __restrict__ wo,
                       const float* __restrict__ w1) {
    int idx = blockIdx.x * blockDim.x + threadIdx.x;
    if (idx < IDS_X) {
        if (idx < BATCH * DD) { g_poolP[idx] = 0.f; g_poolH[idx] = 0.f; }
        size_t i = (size_t)idx * 8;
        float4 a = *reinterpret_cast<const float4*>(x + i);
        float4 b = *reinterpret_cast<const float4*>(x + i + 4);
        uint4 o;
        o.x = h2u(__floats2half2_rn(a.x, a.y));
        o.y = h2u(__floats2half2_rn(a.z, a.w));
        o.z = h2u(__floats2half2_rn(b.x, b.y));
        o.w = h2u(__floats2half2_rn(b.z, b.w));
        *reinterpret_cast<uint4*>(&g_xh[i]) = o;
    } else if (idx < IDS_X + IDS_L) {
        int t = idx - IDS_X;
        int d = t >> 10, c = t & 1023;
        int h = c >> 6, r = c & 63;
        const float* a = wq + (size_t)d * DD + h * 64;
        const float* k = kv + (size_t)r * DD + h * 64;
        float s = 0.f;
        #pragma unroll 16
        for (int j = 0; j < 64; j++) s += a[j] * k[j];
        g_BA[(size_t)d * DD + c] = __float2half_rn(s * 0.125f);
    } else if (idx < IDS_X + IDS_L + IDS_M) {
        int t = idx - IDS_X - IDS_L;
        int row = t >> 10, d = t & 1023;
        int h = row >> 6, r = row & 63;
        const float* kvp = kv + (size_t)r * DD + h * 64;
        float s = 0.f;
        #pragma unroll 8
        for (int j = 0; j < 64; j++) s += kvp[j] * wo[(size_t)(h * 64 + j) * DD + d];
        g_M [(size_t)row * DD + d] = s;
        g_Mh[(size_t)row * DD + d] = __float2half_rn(s);
    } else {
        int t = idx - IDS_X - IDS_L - IDS_M;     // 0..131071
        size_t i = (size_t)t * 8;
        float4 a = *reinterpret_cast<const float4*>(w1 + i);
        float4 b = *reinterpret_cast<const float4*>(w1 + i + 4);
        uint4 o;
        o.x = h2u(__floats2half2_rn(a.x, a.y));
        o.y = h2u(__floats2half2_rn(a.z, a.w));
        o.z = h2u(__floats2half2_rn(b.x, b.y));
        o.w = h2u(__floats2half2_rn(b.z, b.w));
        *reinterpret_cast<uint4*>(&g_w1h[i]) = o;
    }
}

// ------------------------- main fp16 MMA GEMM (K=1024, BK=64, 3-stage) -------------------------

__device__ __forceinline__ void fill_stage(const __half* __restrict__ A,
                                           const __half* __restrict__ Bm,
                                           uint32_t aSm, uint32_t bSm,
                                           int tid, int rowbase, int colbase, int k0) {
    #pragma unroll
    for (int i = 0; i < 4; i++) {
        int e = tid + i * 256;              // 0..1023
        int r = e >> 3, sg = e & 7;
        cp16(aSm + r * (A_ROW_H * 2) + sg * 16,
             A + (size_t)(rowbase + r) * DD + k0 + sg * 8);
    }
    #pragma unroll
    for (int i = 0; i < 4; i++) {
        int e = tid + i * 256;              // 0..1023
        int r = e >> 4, sg = e & 15;
        cp16(bSm + r * (B_ROW_H * 2) + sg * 16,
             Bm + (size_t)(k0 + r) * DD + colbase + sg * 8);
    }
}

// Shared mainloop; acc in caller registers
__device__ __forceinline__ void gemm_mainloop(const __half* __restrict__ A,
                                              const __half* __restrict__ Bm,
                                              uint32_t base, int tid, int lane,
                                              int wm, int wn, int rowbase, int colbase,
                                              float acc[2][8][4]) {
    #pragma unroll
    for (int s = 0; s < NSTAGE - 1; s++) {
        uint32_t aSm = base + s * STAGE_B;
        fill_stage(A, Bm, aSm, aSm + A_STAGE_B, tid, rowbase, colbase, s * BK);
        cp_commit();
    }
    for (int kt = 0; kt < KTILES; kt++) {
        if (kt < KTILES - 1) asm volatile("cp.async.wait_group 1;\n" ::: "memory");
        else                 asm volatile("cp.async.wait_group 0;\n" ::: "memory");
        __syncthreads();
        if (kt + NSTAGE - 1 < KTILES) {
            int s = (kt + NSTAGE - 1) % NSTAGE;
            uint32_t aSm = base + s * STAGE_B;
            fill_stage(A, Bm, aSm, aSm + A_STAGE_B, tid, rowbase, colbase, (kt + NSTAGE - 1) * BK);
            cp_commit();
        }
        const int cur = kt % NSTAGE;
        const uint32_t aSm = base + cur * STAGE_B;
        const uint32_t bSm = aSm + A_STAGE_B;
        #pragma unroll
        for (int ks = 0; ks < 4; ks++) {
            const int k0 = ks * 16;
            uint32_t af[2][4];
            #pragma unroll
            for (int mi = 0; mi < 2; mi++) {
                unsigned ad = aSm + (wm * 32 + mi * 16 + (lane & 15)) * (A_ROW_H * 2)
                            + (k0 + (lane >> 4) * 8) * 2;
                ldsm4(af[mi][0], af[mi][1], af[mi][2], af[mi][3], ad);
            }
            uint32_t bf[8][2];
            #pragma unroll
            for (int nj = 0; nj < 4; nj++) {
                unsigned bd = bSm + (k0 + (lane & 15)) * (B_ROW_H * 2)
                            + (wn * 64 + nj * 16 + (lane >> 4) * 8) * 2;
                uint32_t r0, r1, r2, r3;
                ldsm4t(r0, r1, r2, r3, bd);
                bf[nj * 2][0] = r0; bf[nj * 2][1] = r1;
                bf[nj * 2 + 1][0] = r2; bf[nj * 2 + 1][1] = r3;
            }
            #pragma unroll
            for (int mi = 0; mi < 2; mi++)
                #pragma unroll
                for (int ni = 0; ni < 8; ni++)
                    mma16816(acc[mi][ni], af[mi], bf[ni]);
        }
    }
}

__device__ __forceinline__ void pool_reduce(float acc[2][8][4], float* pool,
                                            int bidx, int cb, int lane) {
    float t0[8], t1[8];
    #pragma unroll
    for (int ni = 0; ni < 8; ni++) {
        t0[ni] = acc[0][ni][0] + acc[0][ni][2] + acc[1][ni][0] + acc[1][ni][2];
        t1[ni] = acc[0][ni][1] + acc[0][ni][3] + acc[1][ni][1] + acc[1][ni][3];
        #pragma unroll
        for (int off = 4; off < 32; off <<= 1) {
            t0[ni] += __shfl_xor_sync(0xffffffffu, t0[ni], off);
            t1[ni] += __shfl_xor_sync(0xffffffffu, t1[ni], off);
        }
    }
    if (lane < 4) {
        float* dst = pool + bidx * DD + cb;
        #pragma unroll
        for (int ni = 0; ni < 8; ni++) {
            atomicAdd(dst + ni * 8,     t0[ni]);
            atomicAdd(dst + ni * 8 + 1, t1[ni]);
        }
    }
}

// Combined GEMM A (y<1024: logits+softmax -> P, poolP) and MW1 (y>=1024: Mh@w1h -> BB)
__global__ __launch_bounds__(256, 2) void k_gemmAW() {
    extern __shared__ __align__(16) char dsm[];
    const uint32_t base = smem_u32(dsm);
    const int tid  = threadIdx.x;
    const int lane = tid & 31;
    const int warp = tid >> 5;
    const int wm = warp & 3;
    const int wn = warp >> 2;
    const int colbase = blockIdx.x * BN;
    const bool isA = blockIdx.y < (NTOK / BM);
    const int rowbase = (isA ? blockIdx.y : blockIdx.y - NTOK / BM) * BM;
    const __half* A  = isA ? g_xh : g_Mh;
    const __half* Bm = isA ? g_BA : g_w1h;
    __half* Out      = isA ? g_P  : g_BB;

    float acc[2][8][4];
    #pragma unroll
    for (int mi = 0; mi < 2; mi++)
        #pragma unroll
        for (int ni = 0; ni < 8; ni++)
            #pragma unroll
            for (int q = 0; q < 4; q++) acc[mi][ni][q] = 0.f;

    gemm_mainloop(A, Bm, base, tid, lane, wm, wn, rowbase, colbase, acc);

    const int cb = colbase + wn * 64 + (lane & 3) * 2;
    if (isA) {
        // softmax over this warp's 64-column chunk (one head)
        #pragma unroll
        for (int mi = 0; mi < 2; mi++) {
            float mx0 = -1e30f, mx1 = -1e30f;
            #pragma unroll
            for (int ni = 0; ni < 8; ni++) {
                mx0 = fmaxf(mx0, fmaxf(acc[mi][ni][0], acc[mi][ni][1]));
                mx1 = fmaxf(mx1, fmaxf(acc[mi][ni][2], acc[mi][ni][3]));
            }
            mx0 = fmaxf(mx0, __shfl_xor_sync(0xffffffffu, mx0, 1));
            mx0 = fmaxf(mx0, __shfl_xor_sync(0xffffffffu, mx0, 2));
            mx1 = fmaxf(mx1, __shfl_xor_sync(0xffffffffu, mx1, 1));
            mx1 = fmaxf(mx1, __shfl_xor_sync(0xffffffffu, mx1, 2));
            float s0 = 0.f, s1 = 0.f;
            #pragma unroll
            for (int ni = 0; ni < 8; ni++) {
                acc[mi][ni][0] = __expf(acc[mi][ni][0] - mx0); s0 += acc[mi][ni][0];
                acc[mi][ni][1] = __expf(acc[mi][ni][1] - mx0); s0 += acc[mi][ni][1];
                acc[mi][ni][2] = __expf(acc[mi][ni][2] - mx1); s1 += acc[mi][ni][2];
                acc[mi][ni][3] = __expf(acc[mi][ni][3] - mx1); s1 += acc[mi][ni][3];
            }
            s0 += __shfl_xor_sync(0xffffffffu, s0, 1);
            s0 += __shfl_xor_sync(0xffffffffu, s0, 2);
            s1 += __shfl_xor_sync(0xffffffffu, s1, 1);
            s1 += __shfl_xor_sync(0xffffffffu, s1, 2);
            float i0 = 1.f / s0, i1 = 1.f / s1;
            int ra = rowbase + wm * 32 + mi * 16 + (lane >> 2);
            #pragma unroll
            for (int ni = 0; ni < 8; ni++) {
                acc[mi][ni][0] *= i0; acc[mi][ni][1] *= i0;
                acc[mi][ni][2] *= i1; acc[mi][ni][3] *= i1;
                *reinterpret_cast<__half2*>(&Out[(size_t)ra * DD + cb + ni * 8]) =
                    __floats2half2_rn(acc[mi][ni][0], acc[mi][ni][1]);
                *reinterpret_cast<__half2*>(&Out[(size_t)(ra + 8) * DD + cb + ni * 8]) =
                    __floats2half2_rn(acc[mi][ni][2], acc[mi][ni][3]);
            }
        }
        pool_reduce(acc, g_poolP, rowbase >> 12, cb, lane);
    } else {
        // plain fp16 store (MW1)
        #pragma unroll
        for (int mi = 0; mi < 2; mi++) {
            int ra = rowbase + wm * 32 + mi * 16 + (lane >> 2);
            #pragma unroll
            for (int ni = 0; ni < 8; ni++) {
                *reinterpret_cast<__half2*>(&Out[(size_t)ra * DD + cb + ni * 8]) =
                    __floats2half2_rn(acc[mi][ni][0], acc[mi][ni][1]);
                *reinterpret_cast<__half2*>(&Out[(size_t)(ra + 8) * DD + cb + ni * 8]) =
                    __floats2half2_rn(acc[mi][ni][2], acc[mi][ni][3]);
            }
        }
    }
}

// GEMM B: H = gelu(P @ MW1 + b1), poolH atomics only (no store)
__global__ __launch_bounds__(256, 2) void k_gemmB(const float* __restrict__ bias) {
    extern __shared__ __align__(16) char dsm[];
    const uint32_t base = smem_u32(dsm);
    const int tid  = threadIdx.x;
    const int lane = tid & 31;
    const int warp = tid >> 5;
    const int wm = warp & 3;
    const int wn = warp >> 2;
    const int rowbase = blockIdx.y * BM;
    const int colbase = blockIdx.x * BN;

    float acc[2][8][4];
    #pragma unroll
    for (int mi = 0; mi < 2; mi++)
        #pragma unroll
        for (int ni = 0; ni < 8; ni++)
            #pragma unroll
            for (int q = 0; q < 4; q++) acc[mi][ni][q] = 0.f;

    gemm_mainloop(g_P, g_BB, base, tid, lane, wm, wn, rowbase, colbase, acc);

    const int cb = colbase + wn * 64 + (lane & 3) * 2;
    #pragma unroll
    for (int mi = 0; mi < 2; mi++) {
        #pragma unroll
        for (int ni = 0; ni < 8; ni++) {
            int c = cb + ni * 8;
            float b0 = bias[c], b1v = bias[c + 1];
            float v0 = acc[mi][ni][0] + b0, v1 = acc[mi][ni][1] + b1v;
            float v2 = acc[mi][ni][2] + b0, v3 = acc[mi][ni][3] + b1v;
            acc[mi][ni][0] = 0.5f * v0 * (1.f + erff(v0 * 0.70710678118654752f));
            acc[mi][ni][1] = 0.5f * v1 * (1.f + erff(v1 * 0.70710678118654752f));
            acc[mi][ni][2] = 0.5f * v2 * (1.f + erff(v2 * 0.70710678118654752f));
            acc[mi][ni][3] = 0.5f * v3 * (1.f + erff(v3 * 0.70710678118654752f));
        }
    }
    pool_reduce(acc, g_poolH, rowbase >> 12, cb, lane);
}

// ------------------------- final -------------------------

__global__ void k_final_init(const float* __restrict__ b2, float* __restrict__ out) {
    int i = blockIdx.x * blockDim.x + threadIdx.x;
    if (i < BATCH * DD) out[i] = b2[i & (DD - 1)];
}

__global__ __launch_bounds__(128) void k_final_acc(const float* __restrict__ w2, float* __restrict__ out) {
    __shared__ float sH[BATCH][64];
    __shared__ float sP[BATCH][64];
    int d = blockIdx.x * 128 + threadIdx.x;
    int k0 = blockIdx.y * 64;
    for (int i = threadIdx.x; i < BATCH * 64; i += 128) {
        int bb = i >> 6, kk = i & 63;
        sH[bb][kk] = g_poolH[bb * DD + k0 + kk];
        sP[bb][kk] = g_poolP[bb * DD + k0 + kk];
    }
    __syncthreads();
    float a[BATCH];
    #pragma unroll
    for (int b = 0; b < BATCH; b++) a[b] = 0.f;
    for (int kk = 0; kk < 64; kk++) {
        float wv = w2[(size_t)(k0 + kk) * DD + d];
        float mv = g_M[(size_t)(k0 + kk) * DD + d];
        #pragma unroll
        for (int b = 0; b < BATCH; b++) a[b] += sH[b][kk] * wv + sP[b][kk] * mv;
    }
    const float inv = 1.0f / (float)SEQ;
    #pragma unroll
    for (int b = 0; b < BATCH; b++) atomicAdd(&out[b * DD + d], a[b] * inv);
}

// ------------------------- launcher -------------------------
extern "C" void kernel_launch(void* const* d_in, const int* in_sizes, int n_in,
                              void* d_out, int out_size) {
    const float* x  = (const float*)d_in[0];
    const float* wq = (const float*)d_in[1];
    const float* kv = (const float*)d_in[2];
    const float* wo = (const float*)d_in[3];
    const float* w1 = (const float*)d_in[4];
    const float* b1 = (const float*)d_in[5];
    const float* w2 = (const float*)d_in[6];
    const float* b2 = (const float*)d_in[7];
    float* out = (float*)d_out;
    (void)in_sizes; (void)n_in; (void)out_size;

    cudaFuncSetAttribute(k_gemmAW, cudaFuncAttributeMaxDynamicSharedMemorySize, SMEM_DYN);
    cudaFuncSetAttribute(k_gemmB,  cudaFuncAttributeMaxDynamicSharedMemorySize, SMEM_DYN);

    dim3 gaw(DD / BN, NTOK / BM + DD / BM);   // (8, 1032): 1024 A-blocks + 8 MW1-blocks
    dim3 gb (DD / BN, NTOK / BM);             // (8, 1024)

    // 0: fused prep
    k_prep<<<IDS_ALL / 256, 256>>>(x, wq, kv, wo, w1);
    // 1: out init (independent)
    k_final_init<<<(BATCH * DD + 255) / 256, 256>>>(b2, out);
    // 2: GEMM A + MW1 combined
    k_gemmAW<<<gaw, 256, SMEM_DYN>>>();
    // 3: GEMM B  (profiled slot)
    k_gemmB<<<gb, 256, SMEM_DYN>>>(b1);
    // 4: final accumulate
    k_final_acc<<<dim3(DD / 128, DD / 64), 128>>>(w2, out);
}

// round 14
// speedup vs baseline: 1.1904x; 1.0890x over previous
#include <cuda_runtime.h>
#include <cuda_fp16.h>
#include <cstdint>
#include <math.h>

// Problem constants
#define DD    1024
#define NTOK  131072      // 32*4096
#define BATCH 32
#define SEQ   4096

// GEMM tile config (fp16, K = 1024)  -- R8-proven shape
#define BM 128
#define BN 128
#define BK 64
#define KTOT 1024
#define KTILES (KTOT / BK)        // 16
#define NSTAGE 3

#define A_ROW_H (BK + 8)           // 72 halves = 144 B
#define B_ROW_H (BN + 8)           // 136 halves = 272 B
#define A_STAGE_B (BM * A_ROW_H * 2)            // 18432
#define B_STAGE_B (BK * B_ROW_H * 2)            // 17408
#define STAGE_B   (A_STAGE_B + B_STAGE_B)       // 35840
#define SMEM_DYN  (NSTAGE * STAGE_B)            // 107520

// fused prep kernel id ranges (all multiples of 256)
#define IDS_X   16777216            // NTOK*DD/8
#define IDS_L   1048576
#define IDS_M   1048576
#define IDS_W1  131072              // DD*DD/8
#define IDS_ALL (IDS_X + IDS_L + IDS_M + IDS_W1)

// ------------------------- device globals (scratch) -------------------------
__device__ __align__(256) __half g_xh [(size_t)NTOK * DD];  // x fp16 [n][k]
__device__ __align__(256) __half g_P  [(size_t)NTOK * DD];  // probs  fp16
__device__ __align__(256) __half g_BA [(size_t)DD * DD];    // L      [k][n] fp16
__device__ __align__(256) __half g_BB [(size_t)DD * DD];    // MW1    [k][n] fp16
__device__ __align__(256) __half g_Mh [(size_t)DD * DD];    // M fp16 [m][k]
__device__ __align__(256) __half g_w1h[(size_t)DD * DD];    // w1 fp16 [k][n]
__device__ __align__(256) float  g_M  [(size_t)DD * DD];    // M fp32 [k][d]
__device__ float g_poolP[BATCH * DD];
__device__ float g_poolH[BATCH * DD];

// ------------------------- helpers -------------------------
__device__ __forceinline__ uint32_t h2u(__half2 v) {
    uint32_t r; memcpy(&r, &v, 4); return r;
}
__device__ __forceinline__ unsigned smem_u32(const void* p) {
    return (unsigned)__cvta_generic_to_shared(p);
}
__device__ __forceinline__ void cp16(unsigned dst, const void* src) {
    asm volatile("cp.async.cg.shared.global [%0], [%1], 16;\n" :: "r"(dst), "l"(src));
}
__device__ __forceinline__ void cp_commit() { asm volatile("cp.async.commit_group;\n"); }

__device__ __forceinline__ void ldsm4(uint32_t &r0, uint32_t &r1, uint32_t &r2, uint32_t &r3, unsigned a) {
    asm volatile("ldmatrix.sync.aligned.m8n8.x4.shared.b16 {%0,%1,%2,%3},[%4];\n"
                 : "=r"(r0), "=r"(r1), "=r"(r2), "=r"(r3) : "r"(a));
}
__device__ __forceinline__ void ldsm4t(uint32_t &r0, uint32_t &r1, uint32_t &r2, uint32_t &r3, unsigned a) {
    asm volatile("ldmatrix.sync.aligned.m8n8.x4.trans.shared.b16 {%0,%1,%2,%3},[%4];\n"
                 : "=r"(r0), "=r"(r1), "=r"(r2), "=r"(r3) : "r"(a));
}
__device__ __forceinline__ void mma16816(float* c, const uint32_t* a, const uint32_t* b) {
    asm volatile("mma.sync.aligned.m16n8k16.row.col.f32.f16.f16.f32 "
                 "{%0,%1,%2,%3},{%4,%5,%6,%7},{%8,%9},{%0,%1,%2,%3};\n"
                 : "+f"(c[0]), "+f"(c[1]), "+f"(c[2]), "+f"(c[3])
                 : "r"(a[0]), "r"(a[1]), "r"(a[2]), "r"(a[3]), "r"(b[0]), "r"(b[1]));
}

// ------------------------- fused prep kernel -------------------------
__global__ void k_prep(const float* __restrict__ x, const float* __restrict__ wq,
                       const float* __restrict__ kv, const float* __restrict__ wo,
                       const float* __restrict__ w1) {
    int idx = blockIdx.x * blockDim.x + threadIdx.x;
    if (idx < IDS_X) {
        if (idx < BATCH * DD) { g_poolP[idx] = 0.f; g_poolH[idx] = 0.f; }
        size_t i = (size_t)idx * 8;
        float4 a = *reinterpret_cast<const float4*>(x + i);
        float4 b = *reinterpret_cast<const float4*>(x + i + 4);
        uint4 o;
        o.x = h2u(__floats2half2_rn(a.x, a.y));
        o.y = h2u(__floats2half2_rn(a.z, a.w));
        o.z = h2u(__floats2half2_rn(b.x, b.y));
        o.w = h2u(__floats2half2_rn(b.z, b.w));
        *reinterpret_cast<uint4*>(&g_xh[i]) = o;
    } else if (idx < IDS_X + IDS_L) {
        int t = idx - IDS_X;
        int d = t >> 10, c = t & 1023;
        int h = c >> 6, r = c & 63;
        const float* a = wq + (size_t)d * DD + h * 64;
        const float* k = kv + (size_t)r * DD + h * 64;
        float s = 0.f;
        #pragma unroll 16
        for (int j = 0; j < 64; j++) s += a[j] * k[j];
        g_BA[(size_t)d * DD + c] = __float2half_rn(s * 0.125f);
    } else if (idx < IDS_X + IDS_L + IDS_M) {
        int t = idx - IDS_X - IDS_L;
        int row = t >> 10, d = t & 1023;
        int h = row >> 6, r = row & 63;
        const float* kvp = kv + (size_t)r * DD + h * 64;
        float s = 0.f;
        #pragma unroll 8
        for (int j = 0; j < 64; j++) s += kvp[j] * wo[(size_t)(h * 64 + j) * DD + d];
        g_M [(size_t)row * DD + d] = s;
        g_Mh[(size_t)row * DD + d] = __float2half_rn(s);
    } else {
        int t = idx - IDS_X - IDS_L - IDS_M;     // 0..131071
        size_t i = (size_t)t * 8;
        float4 a = *reinterpret_cast<const float4*>(w1 + i);
        float4 b = *reinterpret_cast<const float4*>(w1 + i + 4);
        uint4 o;
        o.x = h2u(__floats2half2_rn(a.x, a.y));
        o.y = h2u(__floats2half2_rn(a.z, a.w));
        o.z = h2u(__floats2half2_rn(b.x, b.y));
        o.w = h2u(__floats2half2_rn(b.z, b.w));
        *reinterpret_cast<uint4*>(&g_w1h[i]) = o;
    }
}

// ------------------------- main fp16 MMA GEMM (K=1024, BK=64, 3-stage) -------------------------

__device__ __forceinline__ void fill_stage(const __half* __restrict__ A,
                                           const __half* __restrict__ Bm,
                                           uint32_t aSm, uint32_t bSm,
                                           int tid, int rowbase, int colbase, int k0) {
    #pragma unroll
    for (int i = 0; i < 4; i++) {
        int e = tid + i * 256;              // 0..1023
        int r = e >> 3, sg = e & 7;
        cp16(aSm + r * (A_ROW_H * 2) + sg * 16,
             A + (size_t)(rowbase + r) * DD + k0 + sg * 8);
    }
    #pragma unroll
    for (int i = 0; i < 4; i++) {
        int e = tid + i * 256;              // 0..1023
        int r = e >> 4, sg = e & 15;
        cp16(bSm + r * (B_ROW_H * 2) + sg * 16,
             Bm + (size_t)(k0 + r) * DD + colbase + sg * 8);
    }
}

// Shared mainloop; acc in caller registers.  Fully unrolled over KTILES so all
// stage indices / smem addresses constant-fold (R14 change).
__device__ __forceinline__ void gemm_mainloop(const __half* __restrict__ A,
                                              const __half* __restrict__ Bm,
                                              uint32_t base, int tid, int lane,
                                              int wm, int wn, int rowbase, int colbase,
                                              float acc[2][8][4]) {
    #pragma unroll
    for (int s = 0; s < NSTAGE - 1; s++) {
        uint32_t aSm = base + s * STAGE_B;
        fill_stage(A, Bm, aSm, aSm + A_STAGE_B, tid, rowbase, colbase, s * BK);
        cp_commit();
    }
    #pragma unroll
    for (int kt = 0; kt < KTILES; kt++) {
        if (kt < KTILES - 1) asm volatile("cp.async.wait_group 1;\n" ::: "memory");
        else                 asm volatile("cp.async.wait_group 0;\n" ::: "memory");
        __syncthreads();
        if (kt + NSTAGE - 1 < KTILES) {
            int s = (kt + NSTAGE - 1) % NSTAGE;
            uint32_t aSm = base + s * STAGE_B;
            fill_stage(A, Bm, aSm, aSm + A_STAGE_B, tid, rowbase, colbase, (kt + NSTAGE - 1) * BK);
            cp_commit();
        }
        const int cur = kt % NSTAGE;
        const uint32_t aSm = base + cur * STAGE_B;
        const uint32_t bSm = aSm + A_STAGE_B;
        #pragma unroll
        for (int ks = 0; ks < 4; ks++) {
            const int k0 = ks * 16;
            uint32_t af[2][4];
            #pragma unroll
            for (int mi = 0; mi < 2; mi++) {
                unsigned ad = aSm + (wm * 32 + mi * 16 + (lane & 15)) * (A_ROW_H * 2)
                            + (k0 + (lane >> 4) * 8) * 2;
                ldsm4(af[mi][0], af[mi][1], af[mi][2], af[mi][3], ad);
            }
            uint32_t bf[8][2];
            #pragma unroll
            for (int nj = 0; nj < 4; nj++) {
                unsigned bd = bSm + (k0 + (lane & 15)) * (B_ROW_H * 2)
                            + (wn * 64 + nj * 16 + (lane >> 4) * 8) * 2;
                uint32_t r0, r1, r2, r3;
                ldsm4t(r0, r1, r2, r3, bd);
                bf[nj * 2][0] = r0; bf[nj * 2][1] = r1;
                bf[nj * 2 + 1][0] = r2; bf[nj * 2 + 1][1] = r3;
            }
            #pragma unroll
            for (int mi = 0; mi < 2; mi++)
                #pragma unroll
                for (int ni = 0; ni < 8; ni++)
                    mma16816(acc[mi][ni], af[mi], bf[ni]);
        }
    }
}

__device__ __forceinline__ void pool_reduce(float acc[2][8][4], float* pool,
                                            int bidx, int cb, int lane) {
    float t0[8], t1[8];
    #pragma unroll
    for (int ni = 0; ni < 8; ni++) {
        t0[ni] = acc[0][ni][0] + acc[0][ni][2] + acc[1][ni][0] + acc[1][ni][2];
        t1[ni] = acc[0][ni][1] + acc[0][ni][3] + acc[1][ni][1] + acc[1][ni][3];
        #pragma unroll
        for (int off = 4; off < 32; off <<= 1) {
            t0[ni] += __shfl_xor_sync(0xffffffffu, t0[ni], off);
            t1[ni] += __shfl_xor_sync(0xffffffffu, t1[ni], off);
        }
    }
    if (lane < 4) {
        float* dst = pool + bidx * DD + cb;
        #pragma unroll
        for (int ni = 0; ni < 8; ni++) {
            atomicAdd(dst + ni * 8,     t0[ni]);
            atomicAdd(dst + ni * 8 + 1, t1[ni]);
        }
    }
}

// Combined GEMM A (y<1024: logits+softmax -> P, poolP) and MW1 (y>=1024: Mh@w1h -> BB)
__global__ __launch_bounds__(256, 2) void k_gemmAW() {
    extern __shared__ __align__(16) char dsm[];
    const uint32_t base = smem_u32(dsm);
    const int tid  = threadIdx.x;
    const int lane = tid & 31;
    const int warp = tid >> 5;
    const int wm = warp & 3;
    const int wn = warp >> 2;
    const int colbase = blockIdx.x * BN;
    const bool isA = blockIdx.y < (NTOK / BM);
    const int rowbase = (isA ? blockIdx.y : blockIdx.y - NTOK / BM) * BM;
    const __half* A  = isA ? g_xh : g_Mh;
    const __half* Bm = isA ? g_BA : g_w1h;
    __half* Out      = isA ? g_P  : g_BB;

    float acc[2][8][4];
    #pragma unroll
    for (int mi = 0; mi < 2; mi++)
        #pragma unroll
        for (int ni = 0; ni < 8; ni++)
            #pragma unroll
            for (int q = 0; q < 4; q++) acc[mi][ni][q] = 0.f;

    gemm_mainloop(A, Bm, base, tid, lane, wm, wn, rowbase, colbase, acc);

    const int cb = colbase + wn * 64 + (lane & 3) * 2;
    if (isA) {
        // softmax over this warp's 64-column chunk (one head)
        #pragma unroll
        for (int mi = 0; mi < 2; mi++) {
            float mx0 = -1e30f, mx1 = -1e30f;
            #pragma unroll
            for (int ni = 0; ni < 8; ni++) {
                mx0 = fmaxf(mx0, fmaxf(acc[mi][ni][0], acc[mi][ni][1]));
                mx1 = fmaxf(mx1, fmaxf(acc[mi][ni][2], acc[mi][ni][3]));
            }
            mx0 = fmaxf(mx0, __shfl_xor_sync(0xffffffffu, mx0, 1));
            mx0 = fmaxf(mx0, __shfl_xor_sync(0xffffffffu, mx0, 2));
            mx1 = fmaxf(mx1, __shfl_xor_sync(0xffffffffu, mx1, 1));
            mx1 = fmaxf(mx1, __shfl_xor_sync(0xffffffffu, mx1, 2));
            float s0 = 0.f, s1 = 0.f;
            #pragma unroll
            for (int ni = 0; ni < 8; ni++) {
                acc[mi][ni][0] = __expf(acc[mi][ni][0] - mx0); s0 += acc[mi][ni][0];
                acc[mi][ni][1] = __expf(acc[mi][ni][1] - mx0); s0 += acc[mi][ni][1];
                acc[mi][ni][2] = __expf(acc[mi][ni][2] - mx1); s1 += acc[mi][ni][2];
                acc[mi][ni][3] = __expf(acc[mi][ni][3] - mx1); s1 += acc[mi][ni][3];
            }
            s0 += __shfl_xor_sync(0xffffffffu, s0, 1);
            s0 += __shfl_xor_sync(0xffffffffu, s0, 2);
            s1 += __shfl_xor_sync(0xffffffffu, s1, 1);
            s1 += __shfl_xor_sync(0xffffffffu, s1, 2);
            float i0 = 1.f / s0, i1 = 1.f / s1;
            int ra = rowbase + wm * 32 + mi * 16 + (lane >> 2);
            #pragma unroll
            for (int ni = 0; ni < 8; ni++) {
                acc[mi][ni][0] *= i0; acc[mi][ni][1] *= i0;
                acc[mi][ni][2] *= i1; acc[mi][ni][3] *= i1;
                *reinterpret_cast<__half2*>(&Out[(size_t)ra * DD + cb + ni * 8]) =
                    __floats2half2_rn(acc[mi][ni][0], acc[mi][ni][1]);
                *reinterpret_cast<__half2*>(&Out[(size_t)(ra + 8) * DD + cb + ni * 8]) =
                    __floats2half2_rn(acc[mi][ni][2], acc[mi][ni][3]);
            }
        }
        pool_reduce(acc, g_poolP, rowbase >> 12, cb, lane);
    } else {
        // plain fp16 store (MW1)
        #pragma unroll
        for (int mi = 0; mi < 2; mi++) {
            int ra = rowbase + wm * 32 + mi * 16 + (lane >> 2);
            #pragma unroll
            for (int ni = 0; ni < 8; ni++) {
                *reinterpret_cast<__half2*>(&Out[(size_t)ra * DD + cb + ni * 8]) =
                    __floats2half2_rn(acc[mi][ni][0], acc[mi][ni][1]);
                *reinterpret_cast<__half2*>(&Out[(size_t)(ra + 8) * DD + cb + ni * 8]) =
                    __floats2half2_rn(acc[mi][ni][2], acc[mi][ni][3]);
            }
        }
    }
}

// GEMM B: H = gelu(P @ MW1 + b1), poolH atomics only (no store)
__global__ __launch_bounds__(256, 2) void k_gemmB(const float* __restrict__ bias) {
    extern __shared__ __align__(16) char dsm[];
    const uint32_t base = smem_u32(dsm);
    const int tid  = threadIdx.x;
    const int lane = tid & 31;
    const int warp = tid >> 5;
    const int wm = warp & 3;
    const int wn = warp >> 2;
    const int rowbase = blockIdx.y * BM;
    const int colbase = blockIdx.x * BN;

    float acc[2][8][4];
    #pragma unroll
    for (int mi = 0; mi < 2; mi++)
        #pragma unroll
        for (int ni = 0; ni < 8; ni++)
            #pragma unroll
            for (int q = 0; q < 4; q++) acc[mi][ni][q] = 0.f;

    gemm_mainloop(g_P, g_BB, base, tid, lane, wm, wn, rowbase, colbase, acc);

    const int cb = colbase + wn * 64 + (lane & 3) * 2;
    #pragma unroll
    for (int mi = 0; mi < 2; mi++) {
        #pragma unroll
        for (int ni = 0; ni < 8; ni++) {
            int c = cb + ni * 8;
            float b0 = bias[c], b1v = bias[c + 1];
            float v0 = acc[mi][ni][0] + b0, v1 = acc[mi][ni][1] + b1v;
            float v2 = acc[mi][ni][2] + b0, v3 = acc[mi][ni][3] + b1v;
            acc[mi][ni][0] = 0.5f * v0 * (1.f + erff(v0 * 0.70710678118654752f));
            acc[mi][ni][1] = 0.5f * v1 * (1.f + erff(v1 * 0.70710678118654752f));
            acc[mi][ni][2] = 0.5f * v2 * (1.f + erff(v2 * 0.70710678118654752f));
            acc[mi][ni][3] = 0.5f * v3 * (1.f + erff(v3 * 0.70710678118654752f));
        }
    }
    pool_reduce(acc, g_poolH, rowbase >> 12, cb, lane);
}

// ------------------------- final -------------------------

__global__ void k_final_init(const float* __restrict__ b2, float* __restrict__ out) {
    int i = blockIdx.x * blockDim.x + threadIdx.x;
    if (i < BATCH * DD) out[i] = b2[i & (DD - 1)];
}

__global__ __launch_bounds__(128) void k_final_acc(const float* __restrict__ w2, float* __restrict__ out) {
    __shared__ float sH[BATCH][64];
    __shared__ float sP[BATCH][64];
    int d = blockIdx.x * 128 + threadIdx.x;
    int k0 = blockIdx.y * 64;
    for (int i = threadIdx.x; i < BATCH * 64; i += 128) {
        int bb = i >> 6, kk = i & 63;
        sH[bb][kk] = g_poolH[bb * DD + k0 + kk];
        sP[bb][kk] = g_poolP[bb * DD + k0 + kk];
    }
    __syncthreads();
    float a[BATCH];
    #pragma unroll
    for (int b = 0; b < BATCH; b++) a[b] = 0.f;
    for (int kk = 0; kk < 64; kk++) {
        float wv = w2[(size_t)(k0 + kk) * DD + d];
        float mv = g_M[(size_t)(k0 + kk) * DD + d];
        #pragma unroll
        for (int b = 0; b < BATCH; b++) a[b] += sH[b][kk] * wv + sP[b][kk] * mv;
    }
    const float inv = 1.0f / (float)SEQ;
    #pragma unroll
    for (int b = 0; b < BATCH; b++) atomicAdd(&out[b * DD + d], a[b] * inv);
}

// ------------------------- launcher -------------------------
extern "C" void kernel_launch(void* const* d_in, const int* in_sizes, int n_in,
                              void* d_out, int out_size) {
    const float* x  = (const float*)d_in[0];
    const float* wq = (const float*)d_in[1];
    const float* kv = (const float*)d_in[2];
    const float* wo = (const float*)d_in[3];
    const float* w1 = (const float*)d_in[4];
    const float* b1 = (const float*)d_in[5];
    const float* w2 = (const float*)d_in[6];
    const float* b2 = (const float*)d_in[7];
    float* out = (float*)d_out;
    (void)in_sizes; (void)n_in; (void)out_size;

    cudaFuncSetAttribute(k_gemmAW, cudaFuncAttributeMaxDynamicSharedMemorySize, SMEM_DYN);
    cudaFuncSetAttribute(k_gemmB,  cudaFuncAttributeMaxDynamicSharedMemorySize, SMEM_DYN);

    dim3 gaw(DD / BN, NTOK / BM + DD / BM);   // (8, 1032): 1024 A-blocks + 8 MW1-blocks
    dim3 gb (DD / BN, NTOK / BM);             // (8, 1024)

    // 0: fused prep
    k_prep<<<IDS_ALL / 256, 256>>>(x, wq, kv, wo, w1);
    // 1: out init (independent)
    k_final_init<<<(BATCH * DD + 255) / 256, 256>>>(b2, out);
    // 2: GEMM A + MW1 combined
    k_gemmAW<<<gaw, 256, SMEM_DYN>>>();
    // 3: GEMM B  (profiled slot)
    k_gemmB<<<gb, 256, SMEM_DYN>>>(b1);
    // 4: final accumulate
    k_final_acc<<<dim3(DD / 128, DD / 64), 128>>>(w2, out);
}

// round 15
// speedup vs baseline: 1.2048x; 1.0121x over previous
#include <cuda_runtime.h>
#include <cuda_fp16.h>
#include <cstdint>
#include <math.h>

// Problem constants
#define DD    1024
#define NTOK  131072      // 32*4096
#define BATCH 32
#define SEQ   4096

// GEMM tile config (fp16, K = 1024)  -- R8/R14-proven shape
#define BM 128
#define BN 128
#define BK 64
#define KTOT 1024
#define KTILES (KTOT / BK)        // 16
#define NSTAGE 3

#define A_ROW_H (BK + 8)           // 72 halves = 144 B
#define B_ROW_H (BN + 8)           // 136 halves = 272 B
#define A_STAGE_B (BM * A_ROW_H * 2)            // 18432
#define B_STAGE_B (BK * B_ROW_H * 2)            // 17408
#define STAGE_B   (A_STAGE_B + B_STAGE_B)       // 35840
#define SMEM_DYN  (NSTAGE * STAGE_B)            // 107520

// fused prep kernel id ranges (all multiples of 256)
#define IDS_X   8388608             // NTOK*DD/16 (16 elems per thread)
#define IDS_L   1048576
#define IDS_M   1048576
#define IDS_W1  131072              // DD*DD/8
#define IDS_ALL (IDS_X + IDS_L + IDS_M + IDS_W1)

// ------------------------- device globals (scratch) -------------------------
__device__ __align__(256) __half g_xh [(size_t)NTOK * DD];  // x fp16 [n][k]
__device__ __align__(256) __half g_P  [(size_t)NTOK * DD];  // probs  fp16
__device__ __align__(256) __half g_BA [(size_t)DD * DD];    // L      [k][n] fp16
__device__ __align__(256) __half g_BB [(size_t)DD * DD];    // MW1    [k][n] fp16
__device__ __align__(256) __half g_Mh [(size_t)DD * DD];    // M fp16 [m][k]
__device__ __align__(256) __half g_w1h[(size_t)DD * DD];    // w1 fp16 [k][n]
__device__ __align__(256) float  g_M  [(size_t)DD * DD];    // M fp32 [k][d]
__device__ float g_poolP[BATCH * DD];
__device__ float g_poolH[BATCH * DD];

// ------------------------- helpers -------------------------
__device__ __forceinline__ uint32_t h2u(__half2 v) {
    uint32_t r; memcpy(&r, &v, 4); return r;
}
__device__ __forceinline__ unsigned smem_u32(const void* p) {
    return (unsigned)__cvta_generic_to_shared(p);
}
__device__ __forceinline__ void cp16(unsigned dst, const void* src) {
    asm volatile("cp.async.cg.shared.global [%0], [%1], 16;\n" :: "r"(dst), "l"(src));
}
__device__ __forceinline__ void cp_commit() { asm volatile("cp.async.commit_group;\n"); }

__device__ __forceinline__ void ldsm4(uint32_t &r0, uint32_t &r1, uint32_t &r2, uint32_t &r3, unsigned a) {
    asm volatile("ldmatrix.sync.aligned.m8n8.x4.shared.b16 {%0,%1,%2,%3},[%4];\n"
                 : "=r"(r0), "=r"(r1), "=r"(r2), "=r"(r3) : "r"(a));
}
__device__ __forceinline__ void ldsm4t(uint32_t &r0, uint32_t &r1, uint32_t &r2, uint32_t &r3, unsigned a) {
    asm volatile("ldmatrix.sync.aligned.m8n8.x4.trans.shared.b16 {%0,%1,%2,%3},[%4];\n"
                 : "=r"(r0), "=r"(r1), "=r"(r2), "=r"(r3) : "r"(a));
}
__device__ __forceinline__ void mma16816(float* c, const uint32_t* a, const uint32_t* b) {
    asm volatile("mma.sync.aligned.m16n8k16.row.col.f32.f16.f16.f32 "
                 "{%0,%1,%2,%3},{%4,%5,%6,%7},{%8,%9},{%0,%1,%2,%3};\n"
                 : "+f"(c[0]), "+f"(c[1]), "+f"(c[2]), "+f"(c[3])
                 : "r"(a[0]), "r"(a[1]), "r"(a[2]), "r"(a[3]), "r"(b[0]), "r"(b[1]));
}

// ------------------------- fused prep kernel -------------------------
__global__ void k_prep(const float* __restrict__ x, const float* __restrict__ wq,
                       const float* __restrict__ kv, const float* __restrict__ wo,
                       const float* __restrict__ w1) {
    int idx = blockIdx.x * blockDim.x + threadIdx.x;
    if (idx < IDS_X) {
        if (idx < BATCH * DD) { g_poolP[idx] = 0.f; g_poolH[idx] = 0.f; }
        size_t i = (size_t)idx * 16;
        #pragma unroll
        for (int q = 0; q < 2; q++) {
            float4 a = *reinterpret_cast<const float4*>(x + i + q * 8);
            float4 b = *reinterpret_cast<const float4*>(x + i + q * 8 + 4);
            uint4 o;
            o.x = h2u(__floats2half2_rn(a.x, a.y));
            o.y = h2u(__floats2half2_rn(a.z, a.w));
            o.z = h2u(__floats2half2_rn(b.x, b.y));
            o.w = h2u(__floats2half2_rn(b.z, b.w));
            *reinterpret_cast<uint4*>(&g_xh[i + q * 8]) = o;
        }
    } else if (idx < IDS_X + IDS_L) {
        int t = idx - IDS_X;
        int d = t >> 10, c = t & 1023;
        int h = c >> 6, r = c & 63;
        const float* a = wq + (size_t)d * DD + h * 64;
        const float* k = kv + (size_t)r * DD + h * 64;
        float s = 0.f;
        #pragma unroll 16
        for (int j = 0; j < 64; j++) s += a[j] * k[j];
        g_BA[(size_t)d * DD + c] = __float2half_rn(s * 0.125f);
    } else if (idx < IDS_X + IDS_L + IDS_M) {
        int t = idx - IDS_X - IDS_L;
        int row = t >> 10, d = t & 1023;
        int h = row >> 6, r = row & 63;
        const float* kvp = kv + (size_t)r * DD + h * 64;
        float s = 0.f;
        #pragma unroll 16
        for (int j = 0; j < 64; j++) s += kvp[j] * wo[(size_t)(h * 64 + j) * DD + d];
        g_M [(size_t)row * DD + d] = s;
        g_Mh[(size_t)row * DD + d] = __float2half_rn(s);
    } else {
        int t = idx - IDS_X - IDS_L - IDS_M;     // 0..131071
        size_t i = (size_t)t * 8;
        float4 a = *reinterpret_cast<const float4*>(w1 + i);
        float4 b = *reinterpret_cast<const float4*>(w1 + i + 4);
        uint4 o;
        o.x = h2u(__floats2half2_rn(a.x, a.y));
        o.y = h2u(__floats2half2_rn(a.z, a.w));
        o.z = h2u(__floats2half2_rn(b.x, b.y));
        o.w = h2u(__floats2half2_rn(b.z, b.w));
        *reinterpret_cast<uint4*>(&g_w1h[i]) = o;
    }
}

// ------------------------- main fp16 MMA GEMM (K=1024, BK=64, 3-stage) -------------------------

__device__ __forceinline__ void fill_stage(const __half* __restrict__ A,
                                           const __half* __restrict__ Bm,
                                           uint32_t aSm, uint32_t bSm,
                                           int tid, int rowbase, int colbase, int k0) {
    #pragma unroll
    for (int i = 0; i < 4; i++) {
        int e = tid + i * 256;              // 0..1023
        int r = e >> 3, sg = e & 7;
        cp16(aSm + r * (A_ROW_H * 2) + sg * 16,
             A + (size_t)(rowbase + r) * DD + k0 + sg * 8);
    }
    #pragma unroll
    for (int i = 0; i < 4; i++) {
        int e = tid + i * 256;              // 0..1023
        int r = e >> 4, sg = e & 15;
        cp16(bSm + r * (B_ROW_H * 2) + sg * 16,
             Bm + (size_t)(k0 + r) * DD + colbase + sg * 8);
    }
}

// Shared mainloop; acc in caller registers.  Fully unrolled over KTILES so all
// stage indices / smem addresses constant-fold.
__device__ __forceinline__ void gemm_mainloop(const __half* __restrict__ A,
                                              const __half* __restrict__ Bm,
                                              uint32_t base, int tid, int lane,
                                              int wm, int wn, int rowbase, int colbase,
                                              float acc[2][8][4]) {
    #pragma unroll
    for (int s = 0; s < NSTAGE - 1; s++) {
        uint32_t aSm = base + s * STAGE_B;
        fill_stage(A, Bm, aSm, aSm + A_STAGE_B, tid, rowbase, colbase, s * BK);
        cp_commit();
    }
    #pragma unroll
    for (int kt = 0; kt < KTILES; kt++) {
        if (kt < KTILES - 1) asm volatile("cp.async.wait_group 1;\n" ::: "memory");
        else                 asm volatile("cp.async.wait_group 0;\n" ::: "memory");
        __syncthreads();
        if (kt + NSTAGE - 1 < KTILES) {
            int s = (kt + NSTAGE - 1) % NSTAGE;
            uint32_t aSm = base + s * STAGE_B;
            fill_stage(A, Bm, aSm, aSm + A_STAGE_B, tid, rowbase, colbase, (kt + NSTAGE - 1) * BK);
            cp_commit();
        }
        const int cur = kt % NSTAGE;
        const uint32_t aSm = base + cur * STAGE_B;
        const uint32_t bSm = aSm + A_STAGE_B;
        #pragma unroll
        for (int ks = 0; ks < 4; ks++) {
            const int k0 = ks * 16;
            uint32_t af[2][4];
            #pragma unroll
            for (int mi = 0; mi < 2; mi++) {
                unsigned ad = aSm + (wm * 32 + mi * 16 + (lane & 15)) * (A_ROW_H * 2)
                            + (k0 + (lane >> 4) * 8) * 2;
                ldsm4(af[mi][0], af[mi][1], af[mi][2], af[mi][3], ad);
            }
            uint32_t bf[8][2];
            #pragma unroll
            for (int nj = 0; nj < 4; nj++) {
                unsigned bd = bSm + (k0 + (lane & 15)) * (B_ROW_H * 2)
                            + (wn * 64 + nj * 16 + (lane >> 4) * 8) * 2;
                uint32_t r0, r1, r2, r3;
                ldsm4t(r0, r1, r2, r3, bd);
                bf[nj * 2][0] = r0; bf[nj * 2][1] = r1;
                bf[nj * 2 + 1][0] = r2; bf[nj * 2 + 1][1] = r3;
            }
            #pragma unroll
            for (int mi = 0; mi < 2; mi++)
                #pragma unroll
                for (int ni = 0; ni < 8; ni++)
                    mma16816(acc[mi][ni], af[mi], bf[ni]);
        }
    }
}

__device__ __forceinline__ void pool_reduce(float acc[2][8][4], float* pool,
                                            int bidx, int cb, int lane) {
    float t0[8], t1[8];
    #pragma unroll
    for (int ni = 0; ni < 8; ni++) {
        t0[ni] = acc[0][ni][0] + acc[0][ni][2] + acc[1][ni][0] + acc[1][ni][2];
        t1[ni] = acc[0][ni][1] + acc[0][ni][3] + acc[1][ni][1] + acc[1][ni][3];
        #pragma unroll
        for (int off = 4; off < 32; off <<= 1) {
            t0[ni] += __shfl_xor_sync(0xffffffffu, t0[ni], off);
            t1[ni] += __shfl_xor_sync(0xffffffffu, t1[ni], off);
        }
    }
    if (lane < 4) {
        float* dst = pool + bidx * DD + cb;
        #pragma unroll
        for (int ni = 0; ni < 8; ni++) {
            atomicAdd(dst + ni * 8,     t0[ni]);
            atomicAdd(dst + ni * 8 + 1, t1[ni]);
        }
    }
}

// Combined GEMM A (y<1024: logits+softmax -> P, poolP) and MW1 (y>=1024: Mh@w1h -> BB)
__global__ __launch_bounds__(256, 2) void k_gemmAW() {
    extern __shared__ __align__(16) char dsm[];
    const uint32_t base = smem_u32(dsm);
    const int tid  = threadIdx.x;
    const int lane = tid & 31;
    const int warp = tid >> 5;
    const int wm = warp & 3;
    const int wn = warp >> 2;
    const int colbase = blockIdx.x * BN;
    const bool isA = blockIdx.y < (NTOK / BM);
    const int rowbase = (isA ? blockIdx.y : blockIdx.y - NTOK / BM) * BM;
    const __half* A  = isA ? g_xh : g_Mh;
    const __half* Bm = isA ? g_BA : g_w1h;
    __half* Out      = isA ? g_P  : g_BB;

    float acc[2][8][4];
    #pragma unroll
    for (int mi = 0; mi < 2; mi++)
        #pragma unroll
        for (int ni = 0; ni < 8; ni++)
            #pragma unroll
            for (int q = 0; q < 4; q++) acc[mi][ni][q] = 0.f;

    gemm_mainloop(A, Bm, base, tid, lane, wm, wn, rowbase, colbase, acc);

    const int cb = colbase + wn * 64 + (lane & 3) * 2;
    if (isA) {
        // softmax over this warp's 64-column chunk (one head)
        #pragma unroll
        for (int mi = 0; mi < 2; mi++) {
            float mx0 = -1e30f, mx1 = -1e30f;
            #pragma unroll
            for (int ni = 0; ni < 8; ni++) {
                mx0 = fmaxf(mx0, fmaxf(acc[mi][ni][0], acc[mi][ni][1]));
                mx1 = fmaxf(mx1, fmaxf(acc[mi][ni][2], acc[mi][ni][3]));
            }
            mx0 = fmaxf(mx0, __shfl_xor_sync(0xffffffffu, mx0, 1));
            mx0 = fmaxf(mx0, __shfl_xor_sync(0xffffffffu, mx0, 2));
            mx1 = fmaxf(mx1, __shfl_xor_sync(0xffffffffu, mx1, 1));
            mx1 = fmaxf(mx1, __shfl_xor_sync(0xffffffffu, mx1, 2));
            float s0 = 0.f, s1 = 0.f;
            #pragma unroll
            for (int ni = 0; ni < 8; ni++) {
                acc[mi][ni][0] = __expf(acc[mi][ni][0] - mx0); s0 += acc[mi][ni][0];
                acc[mi][ni][1] = __expf(acc[mi][ni][1] - mx0); s0 += acc[mi][ni][1];
                acc[mi][ni][2] = __expf(acc[mi][ni][2] - mx1); s1 += acc[mi][ni][2];
                acc[mi][ni][3] = __expf(acc[mi][ni][3] - mx1); s1 += acc[mi][ni][3];
            }
            s0 += __shfl_xor_sync(0xffffffffu, s0, 1);
            s0 += __shfl_xor_sync(0xffffffffu, s0, 2);
            s1 += __shfl_xor_sync(0xffffffffu, s1, 1);
            s1 += __shfl_xor_sync(0xffffffffu, s1, 2);
            float i0 = 1.f / s0, i1 = 1.f / s1;
            int ra = rowbase + wm * 32 + mi * 16 + (lane >> 2);
            #pragma unroll
            for (int ni = 0; ni < 8; ni++) {
                acc[mi][ni][0] *= i0; acc[mi][ni][1] *= i0;
                acc[mi][ni][2] *= i1; acc[mi][ni][3] *= i1;
                *reinterpret_cast<__half2*>(&Out[(size_t)ra * DD + cb + ni * 8]) =
                    __floats2half2_rn(acc[mi][ni][0], acc[mi][ni][1]);
                *reinterpret_cast<__half2*>(&Out[(size_t)(ra + 8) * DD + cb + ni * 8]) =
                    __floats2half2_rn(acc[mi][ni][2], acc[mi][ni][3]);
            }
        }
        pool_reduce(acc, g_poolP, rowbase >> 12, cb, lane);
    } else {
        // plain fp16 store (MW1)
        #pragma unroll
        for (int mi = 0; mi < 2; mi++) {
            int ra = rowbase + wm * 32 + mi * 16 + (lane >> 2);
            #pragma unroll
            for (int ni = 0; ni < 8; ni++) {
                *reinterpret_cast<__half2*>(&Out[(size_t)ra * DD + cb + ni * 8]) =
                    __floats2half2_rn(acc[mi][ni][0], acc[mi][ni][1]);
                *reinterpret_cast<__half2*>(&Out[(size_t)(ra + 8) * DD + cb + ni * 8]) =
                    __floats2half2_rn(acc[mi][ni][2], acc[mi][ni][3]);
            }
        }
    }
}

// GEMM B: H = gelu(P @ MW1 + b1), poolH atomics only (no store)
__global__ __launch_bounds__(256, 2) void k_gemmB(const float* __restrict__ bias) {
    extern __shared__ __align__(16) char dsm[];
    const uint32_t base = smem_u32(dsm);
    const int tid  = threadIdx.x;
    const int lane = tid & 31;
    const int warp = tid >> 5;
    const int wm = warp & 3;
    const int wn = warp >> 2;
    const int rowbase = blockIdx.y * BM;
    const int colbase = blockIdx.x * BN;

    float acc[2][8][4];
    #pragma unroll
    for (int mi = 0; mi < 2; mi++)
        #pragma unroll
        for (int ni = 0; ni < 8; ni++)
            #pragma unroll
            for (int q = 0; q < 4; q++) acc[mi][ni][q] = 0.f;

    gemm_mainloop(g_P, g_BB, base, tid, lane, wm, wn, rowbase, colbase, acc);

    const int cb = colbase + wn * 64 + (lane & 3) * 2;
    #pragma unroll
    for (int mi = 0; mi < 2; mi++) {
        #pragma unroll
        for (int ni = 0; ni < 8; ni++) {
            int c = cb + ni * 8;
            float b0 = bias[c], b1v = bias[c + 1];
            float v0 = acc[mi][ni][0] + b0, v1 = acc[mi][ni][1] + b1v;
            float v2 = acc[mi][ni][2] + b0, v3 = acc[mi][ni][3] + b1v;
            acc[mi][ni][0] = 0.5f * v0 * (1.f + erff(v0 * 0.70710678118654752f));
            acc[mi][ni][1] = 0.5f * v1 * (1.f + erff(v1 * 0.70710678118654752f));
            acc[mi][ni][2] = 0.5f * v2 * (1.f + erff(v2 * 0.70710678118654752f));
            acc[mi][ni][3] = 0.5f * v3 * (1.f + erff(v3 * 0.70710678118654752f));
        }
    }
    pool_reduce(acc, g_poolH, rowbase >> 12, cb, lane);
}

// ------------------------- final -------------------------

__global__ void k_final_init(const float* __restrict__ b2, float* __restrict__ out) {
    int i = blockIdx.x * blockDim.x + threadIdx.x;
    if (i < BATCH * DD) out[i] = b2[i & (DD - 1)];
}

__global__ __launch_bounds__(256) void k_final_acc(const float* __restrict__ w2, float* __restrict__ out) {
    __shared__ float sH[BATCH][64];
    __shared__ float sP[BATCH][64];
    int d = blockIdx.x * 256 + threadIdx.x;
    int k0 = blockIdx.y * 64;
    for (int i = threadIdx.x; i < BATCH * 64; i += 256) {
        int bb = i >> 6, kk = i & 63;
        sH[bb][kk] = g_poolH[bb * DD + k0 + kk];
        sP[bb][kk] = g_poolP[bb * DD + k0 + kk];
    }
    __syncthreads();
    float a[BATCH];
    #pragma unroll
    for (int b = 0; b < BATCH; b++) a[b] = 0.f;
    #pragma unroll 4
    for (int kk = 0; kk < 64; kk++) {
        float wv = w2[(size_t)(k0 + kk) * DD + d];
        float mv = g_M[(size_t)(k0 + kk) * DD + d];
        #pragma unroll
        for (int b = 0; b < BATCH; b++) a[b] += sH[b][kk] * wv + sP[b][kk] * mv;
    }
    const float inv = 1.0f / (float)SEQ;
    #pragma unroll
    for (int b = 0; b < BATCH; b++) atomicAdd(&out[b * DD + d], a[b] * inv);
}

// ------------------------- launcher -------------------------
extern "C" void kernel_launch(void* const* d_in, const int* in_sizes, int n_in,
                              void* d_out, int out_size) {
    const float* x  = (const float*)d_in[0];
    const float* wq = (const float*)d_in[1];
    const float* kv = (const float*)d_in[2];
    const float* wo = (const float*)d_in[3];
    const float* w1 = (const float*)d_in[4];
    const float* b1 = (const float*)d_in[5];
    const float* w2 = (const float*)d_in[6];
    const float* b2 = (const float*)d_in[7];
    float* out = (float*)d_out;
    (void)in_sizes; (void)n_in; (void)out_size;

    cudaFuncSetAttribute(k_gemmAW, cudaFuncAttributeMaxDynamicSharedMemorySize, SMEM_DYN);
    cudaFuncSetAttribute(k_gemmB,  cudaFuncAttributeMaxDynamicSharedMemorySize, SMEM_DYN);

    dim3 gaw(DD / BN, NTOK / BM + DD / BM);   // (8, 1032): 1024 A-blocks + 8 MW1-blocks
    dim3 gb (DD / BN, NTOK / BM);             // (8, 1024)

    // 0: fused prep
    k_prep<<<IDS_ALL / 256, 256>>>(x, wq, kv, wo, w1);
    // 1: out init (independent)
    k_final_init<<<(BATCH * DD + 255) / 256, 256>>>(b2, out);
    // 2: GEMM A + MW1 combined
    k_gemmAW<<<gaw, 256, SMEM_DYN>>>();
    // 3: GEMM B  (profiled slot)
    k_gemmB<<<gb, 256, SMEM_DYN>>>(b1);
    // 4: final accumulate
    k_final_acc<<<dim3(DD / 256, DD / 64), 256>>>(w2, out);
}

// round 17
// speedup vs baseline: 1.3657x; 1.1336x over previous
#include <cuda_runtime.h>
#include <cuda_fp16.h>
#include <cstdint>
#include <math.h>

// Problem constants
#define DD    1024
#define NTOK  131072      // 32*4096
#define BATCH 32
#define SEQ   4096

// GEMM tile config (fp16, K = 1024)  -- R8/R14-proven shape
#define BM 128
#define BN 128
#define BK 64
#define KTOT 1024
#define KTILES (KTOT / BK)        // 16
#define NSTAGE 3

#define A_ROW_H (BK + 8)           // 72 halves = 144 B
#define B_ROW_H (BN + 8)           // 136 halves = 272 B
#define A_STAGE_B (BM * A_ROW_H * 2)            // 18432
#define B_STAGE_B (BK * B_ROW_H * 2)            // 17408
#define STAGE_B   (A_STAGE_B + B_STAGE_B)       // 35840
#define SMEM_DYN  (NSTAGE * STAGE_B)            // 107520

// fused prep kernel id ranges (all multiples of 256); L handled by k_buildL
#define IDS_X   8388608             // NTOK*DD/16 (16 elems per thread)
#define IDS_M   1048576
#define IDS_W1  131072              // DD*DD/8
#define IDS_ALL (IDS_X + IDS_M + IDS_W1)

// ------------------------- device globals (scratch) -------------------------
__device__ __align__(256) __half g_xh [(size_t)NTOK * DD];  // x fp16 [n][k]
__device__ __align__(256) __half g_P  [(size_t)NTOK * DD];  // probs  fp16
__device__ __align__(256) __half g_BA [(size_t)DD * DD];    // L      [k][n] fp16
__device__ __align__(256) __half g_BB [(size_t)DD * DD];    // MW1    [k][n] fp16
__device__ __align__(256) __half g_Mh [(size_t)DD * DD];    // M fp16 [m][k]
__device__ __align__(256) __half g_w1h[(size_t)DD * DD];    // w1 fp16 [k][n]
__device__ __align__(256) float  g_M  [(size_t)DD * DD];    // M fp32 [k][d]
__device__ float g_poolP[BATCH * DD];
__device__ float g_poolH[BATCH * DD];

// ------------------------- helpers -------------------------
__device__ __forceinline__ uint32_t h2u(__half2 v) {
    uint32_t r; memcpy(&r, &v, 4); return r;
}
__device__ __forceinline__ unsigned smem_u32(const void* p) {
    return (unsigned)__cvta_generic_to_shared(p);
}
__device__ __forceinline__ void cp16(unsigned dst, const void* src) {
    asm volatile("cp.async.cg.shared.global [%0], [%1], 16;\n" :: "r"(dst), "l"(src));
}
__device__ __forceinline__ void cp_commit() { asm volatile("cp.async.commit_group;\n"); }

__device__ __forceinline__ void ldsm4(uint32_t &r0, uint32_t &r1, uint32_t &r2, uint32_t &r3, unsigned a) {
    asm volatile("ldmatrix.sync.aligned.m8n8.x4.shared.b16 {%0,%1,%2,%3},[%4];\n"
                 : "=r"(r0), "=r"(r1), "=r"(r2), "=r"(r3) : "r"(a));
}
__device__ __forceinline__ void ldsm4t(uint32_t &r0, uint32_t &r1, uint32_t &r2, uint32_t &r3, unsigned a) {
    asm volatile("ldmatrix.sync.aligned.m8n8.x4.trans.shared.b16 {%0,%1,%2,%3},[%4];\n"
                 : "=r"(r0), "=r"(r1), "=r"(r2), "=r"(r3) : "r"(a));
}
__device__ __forceinline__ void mma16816(float* c, const uint32_t* a, const uint32_t* b) {
    asm volatile("mma.sync.aligned.m16n8k16.row.col.f32.f16.f16.f32 "
                 "{%0,%1,%2,%3},{%4,%5,%6,%7},{%8,%9},{%0,%1,%2,%3};\n"
                 : "+f"(c[0]), "+f"(c[1]), "+f"(c[2]), "+f"(c[3])
                 : "r"(a[0]), "r"(a[1]), "r"(a[2]), "r"(a[3]), "r"(b[0]), "r"(b[1]));
}

// ------------------------- L build: smem-tiled micro-GEMM -------------------------
// One block per (head h, 64-row d-group).  L[d][h*64+r] = 0.125 * wq[d,h*64:]. kv[r,h*64:]
__global__ __launch_bounds__(256) void k_buildL(const float* __restrict__ wq,
                                                const float* __restrict__ kv) {
    __shared__ float wqs[64][65];
    __shared__ float kvs[64][65];
    const int h = blockIdx.x;
    const int d0 = blockIdx.y * 64;
    const int tid = threadIdx.x;
    #pragma unroll
    for (int rep = 0; rep < 16; rep++) {
        int e = tid + rep * 256;            // 0..4095
        int i = e >> 6, j = e & 63;
        wqs[i][j] = wq[(size_t)(d0 + i) * DD + h * 64 + j];
        kvs[i][j] = kv[(size_t)i * DD + h * 64 + j];
    }
    __syncthreads();
    const int dl = (tid >> 4) * 4;          // 0,4,...,60
    const int rl = (tid & 15) * 4;          // 0,4,...,60
    float acc[4][4] = {};
    for (int j = 0; j < 64; j++) {
        float a0 = wqs[dl][j], a1 = wqs[dl + 1][j], a2 = wqs[dl + 2][j], a3 = wqs[dl + 3][j];
        float b0 = kvs[rl][j], b1 = kvs[rl + 1][j], b2 = kvs[rl + 2][j], b3 = kvs[rl + 3][j];
        acc[0][0] += a0 * b0; acc[0][1] += a0 * b1; acc[0][2] += a0 * b2; acc[0][3] += a0 * b3;
        acc[1][0] += a1 * b0; acc[1][1] += a1 * b1; acc[1][2] += a1 * b2; acc[1][3] += a1 * b3;
        acc[2][0] += a2 * b0; acc[2][1] += a2 * b1; acc[2][2] += a2 * b2; acc[2][3] += a2 * b3;
        acc[3][0] += a3 * b0; acc[3][1] += a3 * b1; acc[3][2] += a3 * b2; acc[3][3] += a3 * b3;
    }
    #pragma unroll
    for (int i = 0; i < 4; i++) {
        __half2 p0 = __floats2half2_rn(acc[i][0] * 0.125f, acc[i][1] * 0.125f);
        __half2 p1 = __floats2half2_rn(acc[i][2] * 0.125f, acc[i][3] * 0.125f);
        __half* dst = &g_BA[(size_t)(d0 + dl + i) * DD + h * 64 + rl];
        *reinterpret_cast<__half2*>(dst)     = p0;
        *reinterpret_cast<__half2*>(dst + 2) = p1;
    }
}

// ------------------------- fused prep kernel (x, M, w1) -------------------------
__global__ void k_prep(const float* __restrict__ x, const float* __restrict__ kv,
                       const float* __restrict__ wo, const float* __restrict__ w1) {
    int idx = blockIdx.x * blockDim.x + threadIdx.x;
    if (idx < IDS_X) {
        if (idx < BATCH * DD) { g_poolP[idx] = 0.f; g_poolH[idx] = 0.f; }
        size_t i = (size_t)idx * 16;
        #pragma unroll
        for (int q = 0; q < 2; q++) {
            float4 a = *reinterpret_cast<const float4*>(x + i + q * 8);
            float4 b = *reinterpret_cast<const float4*>(x + i + q * 8 + 4);
            uint4 o;
            o.x = h2u(__floats2half2_rn(a.x, a.y));
            o.y = h2u(__floats2half2_rn(a.z, a.w));
            o.z = h2u(__floats2half2_rn(b.x, b.y));
            o.w = h2u(__floats2half2_rn(b.z, b.w));
            *reinterpret_cast<uint4*>(&g_xh[i + q * 8]) = o;
        }
    } else if (idx < IDS_X + IDS_M) {
        int t = idx - IDS_X;
        int row = t >> 10, d = t & 1023;
        int h = row >> 6, r = row & 63;
        const float* kvp = kv + (size_t)r * DD + h * 64;
        float s = 0.f;
        #pragma unroll 16
        for (int j = 0; j < 64; j++) s += kvp[j] * wo[(size_t)(h * 64 + j) * DD + d];
        g_M [(size_t)row * DD + d] = s;
        g_Mh[(size_t)row * DD + d] = __float2half_rn(s);
    } else {
        int t = idx - IDS_X - IDS_M;             // 0..131071
        size_t i = (size_t)t * 8;
        float4 a = *reinterpret_cast<const float4*>(w1 + i);
        float4 b = *reinterpret_cast<const float4*>(w1 + i + 4);
        uint4 o;
        o.x = h2u(__floats2half2_rn(a.x, a.y));
        o.y = h2u(__floats2half2_rn(a.z, a.w));
        o.z = h2u(__floats2half2_rn(b.x, b.y));
        o.w = h2u(__floats2half2_rn(b.z, b.w));
        *reinterpret_cast<uint4*>(&g_w1h[i]) = o;
    }
}

// ------------------------- main fp16 MMA GEMM (K=1024, BK=64, 3-stage) -------------------------

__device__ __forceinline__ void fill_stage(const __half* __restrict__ A,
                                           const __half* __restrict__ Bm,
                                           uint32_t aSm, uint32_t bSm,
                                           int tid, int rowbase, int colbase, int k0) {
    #pragma unroll
    for (int i = 0; i < 4; i++) {
        int e = tid + i * 256;              // 0..1023
        int r = e >> 3, sg = e & 7;
        cp16(aSm + r * (A_ROW_H * 2) + sg * 16,
             A + (size_t)(rowbase + r) * DD + k0 + sg * 8);
    }
    #pragma unroll
    for (int i = 0; i < 4; i++) {
        int e = tid + i * 256;              // 0..1023
        int r = e >> 4, sg = e & 15;
        cp16(bSm + r * (B_ROW_H * 2) + sg * 16,
             Bm + (size_t)(k0 + r) * DD + colbase + sg * 8);
    }
}

// Shared mainloop; acc in caller registers.  Fully unrolled over KTILES.
__device__ __forceinline__ void gemm_mainloop(const __half* __restrict__ A,
                                              const __half* __restrict__ Bm,
                                              uint32_t base, int tid, int lane,
                                              int wm, int wn, int rowbase, int colbase,
                                              float acc[2][8][4]) {
    #pragma unroll
    for (int s = 0; s < NSTAGE - 1; s++) {
        uint32_t aSm = base + s * STAGE_B;
        fill_stage(A, Bm, aSm, aSm + A_STAGE_B, tid, rowbase, colbase, s * BK);
        cp_commit();
    }
    #pragma unroll
    for (int kt = 0; kt < KTILES; kt++) {
        if (kt < KTILES - 1) asm volatile("cp.async.wait_group 1;\n" ::: "memory");
        else                 asm volatile("cp.async.wait_group 0;\n" ::: "memory");
        __syncthreads();
        if (kt + NSTAGE - 1 < KTILES) {
            int s = (kt + NSTAGE - 1) % NSTAGE;
            uint32_t aSm = base + s * STAGE_B;
            fill_stage(A, Bm, aSm, aSm + A_STAGE_B, tid, rowbase, colbase, (kt + NSTAGE - 1) * BK);
            cp_commit();
        }
        const int cur = kt % NSTAGE;
        const uint32_t aSm = base + cur * STAGE_B;
        const uint32_t bSm = aSm + A_STAGE_B;
        #pragma unroll
        for (int ks = 0; ks < 4; ks++) {
            const int k0 = ks * 16;
            uint32_t af[2][4];
            #pragma unroll
            for (int mi = 0; mi < 2; mi++) {
                unsigned ad = aSm + (wm * 32 + mi * 16 + (lane & 15)) * (A_ROW_H * 2)
                            + (k0 + (lane >> 4) * 8) * 2;
                ldsm4(af[mi][0], af[mi][1], af[mi][2], af[mi][3], ad);
            }
            uint32_t bf[8][2];
            #pragma unroll
            for (int nj = 0; nj < 4; nj++) {
                unsigned bd = bSm + (k0 + (lane & 15)) * (B_ROW_H * 2)
                            + (wn * 64 + nj * 16 + (lane >> 4) * 8) * 2;
                uint32_t r0, r1, r2, r3;
                ldsm4t(r0, r1, r2, r3, bd);
                bf[nj * 2][0] = r0; bf[nj * 2][1] = r1;
                bf[nj * 2 + 1][0] = r2; bf[nj * 2 + 1][1] = r3;
            }
            #pragma unroll
            for (int mi = 0; mi < 2; mi++)
                #pragma unroll
                for (int ni = 0; ni < 8; ni++)
                    mma16816(acc[mi][ni], af[mi], bf[ni]);
        }
    }
}

__device__ __forceinline__ void pool_reduce(float acc[2][8][4], float* pool,
                                            int bidx, int cb, int lane) {
    float t0[8], t1[8];
    #pragma unroll
    for (int ni = 0; ni < 8; ni++) {
        t0[ni] = acc[0][ni][0] + acc[0][ni][2] + acc[1][ni][0] + acc[1][ni][2];
        t1[ni] = acc[0][ni][1] + acc[0][ni][3] + acc[1][ni][1] + acc[1][ni][3];
        #pragma unroll
        for (int off = 4; off < 32; off <<= 1) {
            t0[ni] += __shfl_xor_sync(0xffffffffu, t0[ni], off);
            t1[ni] += __shfl_xor_sync(0xffffffffu, t1[ni], off);
        }
    }
    if (lane < 4) {
        float* dst = pool + bidx * DD + cb;
        #pragma unroll
        for (int ni = 0; ni < 8; ni++) {
            atomicAdd(dst + ni * 8,     t0[ni]);
            atomicAdd(dst + ni * 8 + 1, t1[ni]);
        }
    }
}

// Combined GEMM A (y<1024: logits+softmax -> P, poolP) and MW1 (y>=1024: Mh@w1h -> BB)
__global__ __launch_bounds__(256, 2) void k_gemmAW() {
    extern __shared__ __align__(16) char dsm[];
    const uint32_t base = smem_u32(dsm);
    const int tid  = threadIdx.x;
    const int lane = tid & 31;
    const int warp = tid >> 5;
    const int wm = warp & 3;
    const int wn = warp >> 2;
    const int colbase = blockIdx.x * BN;
    const bool isA = blockIdx.y < (NTOK / BM);
    const int rowbase = (isA ? blockIdx.y : blockIdx.y - NTOK / BM) * BM;
    const __half* A  = isA ? g_xh : g_Mh;
    const __half* Bm = isA ? g_BA : g_w1h;
    __half* Out      = isA ? g_P  : g_BB;

    float acc[2][8][4];
    #pragma unroll
    for (int mi = 0; mi < 2; mi++)
        #pragma unroll
        for (int ni = 0; ni < 8; ni++)
            #pragma unroll
            for (int q = 0; q < 4; q++) acc[mi][ni][q] = 0.f;

    gemm_mainloop(A, Bm, base, tid, lane, wm, wn, rowbase, colbase, acc);

    const int cb = colbase + wn * 64 + (lane & 3) * 2;
    if (isA) {
        // softmax over this warp's 64-column chunk (one head)
        #pragma unroll
        for (int mi = 0; mi < 2; mi++) {
            float mx0 = -1e30f, mx1 = -1e30f;
            #pragma unroll
            for (int ni = 0; ni < 8; ni++) {
                mx0 = fmaxf(mx0, fmaxf(acc[mi][ni][0], acc[mi][ni][1]));
                mx1 = fmaxf(mx1, fmaxf(acc[mi][ni][2], acc[mi][ni][3]));
            }
            mx0 = fmaxf(mx0, __shfl_xor_sync(0xffffffffu, mx0, 1));
            mx0 = fmaxf(mx0, __shfl_xor_sync(0xffffffffu, mx0, 2));
            mx1 = fmaxf(mx1, __shfl_xor_sync(0xffffffffu, mx1, 1));
            mx1 = fmaxf(mx1, __shfl_xor_sync(0xffffffffu, mx1, 2));
            float s0 = 0.f, s1 = 0.f;
            #pragma unroll
            for (int ni = 0; ni < 8; ni++) {
                acc[mi][ni][0] = __expf(acc[mi][ni][0] - mx0); s0 += acc[mi][ni][0];
                acc[mi][ni][1] = __expf(acc[mi][ni][1] - mx0); s0 += acc[mi][ni][1];
                acc[mi][ni][2] = __expf(acc[mi][ni][2] - mx1); s1 += acc[mi][ni][2];
                acc[mi][ni][3] = __expf(acc[mi][ni][3] - mx1); s1 += acc[mi][ni][3];
            }
            s0 += __shfl_xor_sync(0xffffffffu, s0, 1);
            s0 += __shfl_xor_sync(0xffffffffu, s0, 2);
            s1 += __shfl_xor_sync(0xffffffffu, s1, 1);
            s1 += __shfl_xor_sync(0xffffffffu, s1, 2);
            float i0 = 1.f / s0, i1 = 1.f / s1;
            int ra = rowbase + wm * 32 + mi * 16 + (lane >> 2);
            #pragma unroll
            for (int ni = 0; ni < 8; ni++) {
                acc[mi][ni][0] *= i0; acc[mi][ni][1] *= i0;
                acc[mi][ni][2] *= i1; acc[mi][ni][3] *= i1;
                *reinterpret_cast<__half2*>(&Out[(size_t)ra * DD + cb + ni * 8]) =
                    __floats2half2_rn(acc[mi][ni][0], acc[mi][ni][1]);
                *reinterpret_cast<__half2*>(&Out[(size_t)(ra + 8) * DD + cb + ni * 8]) =
                    __floats2half2_rn(acc[mi][ni][2], acc[mi][ni][3]);
            }
        }
        pool_reduce(acc, g_poolP, rowbase >> 12, cb, lane);
    } else {
        // plain fp16 store (MW1)
        #pragma unroll
        for (int mi = 0; mi < 2; mi++) {
            int ra = rowbase + wm * 32 + mi * 16 + (lane >> 2);
            #pragma unroll
            for (int ni = 0; ni < 8; ni++) {
                *reinterpret_cast<__half2*>(&Out[(size_t)ra * DD + cb + ni * 8]) =
                    __floats2half2_rn(acc[mi][ni][0], acc[mi][ni][1]);
                *reinterpret_cast<__half2*>(&Out[(size_t)(ra + 8) * DD + cb + ni * 8]) =
                    __floats2half2_rn(acc[mi][ni][2], acc[mi][ni][3]);
            }
        }
    }
}

// GEMM B: H = gelu(P @ MW1 + b1), poolH atomics only (no store)
__global__ __launch_bounds__(256, 2) void k_gemmB(const float* __restrict__ bias) {
    extern __shared__ __align__(16) char dsm[];
    const uint32_t base = smem_u32(dsm);
    const int tid  = threadIdx.x;
    const int lane = tid & 31;
    const int warp = tid >> 5;
    const int wm = warp & 3;
    const int wn = warp >> 2;
    const int rowbase = blockIdx.y * BM;
    const int colbase = blockIdx.x * BN;

    float acc[2][8][4];
    #pragma unroll
    for (int mi = 0; mi < 2; mi++)
        #pragma unroll
        for (int ni = 0; ni < 8; ni++)
            #pragma unroll
            for (int q = 0; q < 4; q++) acc[mi][ni][q] = 0.f;

    gemm_mainloop(g_P, g_BB, base, tid, lane, wm, wn, rowbase, colbase, acc);

    const int cb = colbase + wn * 64 + (lane & 3) * 2;
    #pragma unroll
    for (int mi = 0; mi < 2; mi++) {
        #pragma unroll
        for (int ni = 0; ni < 8; ni++) {
            int c = cb + ni * 8;
            float b0 = bias[c], b1v = bias[c + 1];
            float v0 = acc[mi][ni][0] + b0, v1 = acc[mi][ni][1] + b1v;
            float v2 = acc[mi][ni][2] + b0, v3 = acc[mi][ni][3] + b1v;
            acc[mi][ni][0] = 0.5f * v0 * (1.f + erff(v0 * 0.70710678118654752f));
            acc[mi][ni][1] = 0.5f * v1 * (1.f + erff(v1 * 0.70710678118654752f));
            acc[mi][ni][2] = 0.5f * v2 * (1.f + erff(v2 * 0.70710678118654752f));
            acc[mi][ni][3] = 0.5f * v3 * (1.f + erff(v3 * 0.70710678118654752f));
        }
    }
    pool_reduce(acc, g_poolH, rowbase >> 12, cb, lane);
}

// ------------------------- final -------------------------

__global__ void k_final_init(const float* __restrict__ b2, float* __restrict__ out) {
    int i = blockIdx.x * blockDim.x + threadIdx.x;
    if (i < BATCH * DD) out[i] = b2[i & (DD - 1)];
}

__global__ __launch_bounds__(256) void k_final_acc(const float* __restrict__ w2, float* __restrict__ out) {
    __shared__ float sH[BATCH][64];
    __shared__ float sP[BATCH][64];
    int d = blockIdx.x * 256 + threadIdx.x;
    int k0 = blockIdx.y * 64;
    for (int i = threadIdx.x; i < BATCH * 64; i += 256) {
        int bb = i >> 6, kk = i & 63;
        sH[bb][kk] = g_poolH[bb * DD + k0 + kk];
        sP[bb][kk] = g_poolP[bb * DD + k0 + kk];
    }
    __syncthreads();
    float a[BATCH];
    #pragma unroll
    for (int b = 0; b < BATCH; b++) a[b] = 0.f;
    #pragma unroll 4
    for (int kk = 0; kk < 64; kk++) {
        float wv = w2[(size_t)(k0 + kk) * DD + d];
        float mv = g_M[(size_t)(k0 + kk) * DD + d];
        #pragma unroll
        for (int b = 0; b < BATCH; b++) a[b] += sH[b][kk] * wv + sP[b][kk] * mv;
    }
    const float inv = 1.0f / (float)SEQ;
    #pragma unroll
    for (int b = 0; b < BATCH; b++) atomicAdd(&out[b * DD + d], a[b] * inv);
}

// ------------------------- launcher -------------------------
extern "C" void kernel_launch(void* const* d_in, const int* in_sizes, int n_in,
                              void* d_out, int out_size) {
    const float* x  = (const float*)d_in[0];
    const float* wq = (const float*)d_in[1];
    const float* kv = (const float*)d_in[2];
    const float* wo = (const float*)d_in[3];
    const float* w1 = (const float*)d_in[4];
    const float* b1 = (const float*)d_in[5];
    const float* w2 = (const float*)d_in[6];
    const float* b2 = (const float*)d_in[7];
    float* out = (float*)d_out;
    (void)in_sizes; (void)n_in; (void)out_size;

    cudaFuncSetAttribute(k_gemmAW, cudaFuncAttributeMaxDynamicSharedMemorySize, SMEM_DYN);
    cudaFuncSetAttribute(k_gemmB,  cudaFuncAttributeMaxDynamicSharedMemorySize, SMEM_DYN);

    dim3 gaw(DD / BN, NTOK / BM + DD / BM);   // (8, 1032): 1024 A-blocks + 8 MW1-blocks
    dim3 gb (DD / BN, NTOK / BM);             // (8, 1024)

    // 0: fused prep (x->fp16 + pool zero + M/Mh + w1->fp16)
    k_prep<<<IDS_ALL / 256, 256>>>(x, kv, wo, w1);
    // 1: L build (smem-tiled)
    k_buildL<<<dim3(16, 16), 256>>>(wq, kv);
    // 2: out init (independent)
    k_final_init<<<(BATCH * DD + 255) / 256, 256>>>(b2, out);
    // 3: GEMM A + MW1 combined (profiled slot)
    k_gemmAW<<<gaw, 256, SMEM_DYN>>>();
    // 4: GEMM B
    k_gemmB<<<gb, 256, SMEM_DYN>>>(b1);
    // 5: final accumulate
    k_final_acc<<<dim3(DD / 256, DD / 64), 256>>>(w2, out);
}